// round 3
// baseline (speedup 1.0000x reference)
#include <cuda_runtime.h>
#include <math.h>
#include <stdint.h>

// ---------------------------------------------------------------------------
// Problem constants
// ---------------------------------------------------------------------------
#define NBATCH 2
#define OD 8
#define OH 28
#define OW 28
#define S_OUT 6272              // 8*28*28
#define NS 12544                // NBATCH * S_OUT

__device__ float g_cols[43352064];   // max 3456 * NS
__device__ float g_off1[8128512];    // 648  * NS
__device__ float g_off2[16257024];   // 1296 * NS
__device__ float g_out1[1605632];    // 128  * NS
__device__ float g_out2[1605632];    // 128  * NS
__device__ float g_res[802816];      // 64   * NS
__device__ float g_mean[128];
__device__ float g_istd[128];

// ---------------------------------------------------------------------------
// maxpool3d k3 s2 p1 on x -> residual [64][NS]
// ---------------------------------------------------------------------------
__global__ void maxpool_kernel(const float* __restrict__ x, float* __restrict__ res) {
    int i = blockIdx.x * blockDim.x + threadIdx.x;
    if (i >= 64 * NS) return;
    int ns = i % NS;
    int c  = i / NS;
    int n  = ns / S_OUT;
    int s  = ns % S_OUT;
    int od = s / (OH * OW);
    int oh = (s / OW) % OH;
    int ow = s % OW;
    const float* xp = x + ((size_t)(n * 64 + c)) * 16 * 56 * 56;
    int d0 = od * 2 - 1, h0 = oh * 2 - 1, w0 = ow * 2 - 1;
    int dlo = d0 < 0 ? 0 : d0, dhi = d0 + 2 > 15 ? 15 : d0 + 2;
    int hlo = h0 < 0 ? 0 : h0, hhi = h0 + 2 > 55 ? 55 : h0 + 2;
    int wlo = w0 < 0 ? 0 : w0, whi = w0 + 2 > 55 ? 55 : w0 + 2;
    float m = -INFINITY;
    for (int dd = dlo; dd <= dhi; dd++)
        for (int hh = hlo; hh <= hhi; hh++)
            for (int ww = wlo; ww <= whi; ww++)
                m = fmaxf(m, xp[(dd * 56 + hh) * 56 + ww]);
    res[(size_t)c * NS + ns] = m;
}

// ---------------------------------------------------------------------------
// Regular im2col (3x3x3, pad 1).
// ---------------------------------------------------------------------------
__global__ void im2col_kernel(const float* __restrict__ in, float* __restrict__ cols,
                              int C, int Din, int Hin, int Win, int stride, int ncdhw) {
    long long i = (long long)blockIdx.x * blockDim.x + threadIdx.x;
    long long total = (long long)C * 27 * NS;
    if (i >= total) return;
    int ns  = (int)(i % NS);
    int ct  = (int)(i / NS);
    int tap = ct % 27;
    int c   = ct / 27;
    int n   = ns / S_OUT;
    int s   = ns % S_OUT;
    int od = s / (OH * OW);
    int oh = (s / OW) % OH;
    int ow = s % OW;
    int kd = tap / 9, kh = (tap / 3) % 3, kw = tap % 3;
    int id = od * stride - 1 + kd;
    int ih = oh * stride - 1 + kh;
    int iw = ow * stride - 1 + kw;
    float v = 0.f;
    if (id >= 0 && id < Din && ih >= 0 && ih < Hin && iw >= 0 && iw < Win) {
        size_t Sin = (size_t)Din * Hin * Win;
        size_t base = ncdhw ? ((size_t)(n * C + c)) * Sin
                            : ((size_t)c * NBATCH + n) * Sin;
        v = in[base + ((size_t)id * Hin + ih) * Win + iw];
    }
    cols[(size_t)ct * NS + ns] = v;
}

// ---------------------------------------------------------------------------
// Deformable im2col (one thread per (group, tap, ns); reuses corner
// weights/indices across the 8 channels of the group).
// ---------------------------------------------------------------------------
__global__ void deform_im2col_kernel(const float* __restrict__ in,
                                     const float* __restrict__ off,
                                     float* __restrict__ cols,
                                     int C, int G, int Din, int Hin, int Win,
                                     int stride, int ncdhw) {
    long long i = (long long)blockIdx.x * blockDim.x + threadIdx.x;
    long long total = (long long)G * 27 * NS;
    if (i >= total) return;
    int ns  = (int)(i % NS);
    int gt  = (int)(i / NS);
    int tap = gt % 27;
    int g   = gt / 27;
    int n   = ns / S_OUT;
    int s   = ns % S_OUT;
    int od = s / (OH * OW);
    int oh = (s / OW) % OH;
    int ow = s % OW;
    int kd = tap / 9, kh = (tap / 3) % 3, kw = tap % 3;

    size_t ob = ((size_t)(g * 3) * 27 + tap) * NS + ns;
    float pd = off[ob]                     + (float)(od * stride - 1 + kd);
    float ph = off[ob + (size_t)27 * NS]   + (float)(oh * stride - 1 + kh);
    float pw = off[ob + (size_t)54 * NS]   + (float)(ow * stride - 1 + kw);

    float d0f = floorf(pd), h0f = floorf(ph), w0f = floorf(pw);
    int d0 = (int)d0f, h0 = (int)h0f, w0 = (int)w0f;
    float fd = pd - d0f, fh = ph - h0f, fw = pw - w0f;

    float wt8[8];
    int   idx8[8];
    int Sin = Din * Hin * Win;
#pragma unroll
    for (int cr = 0; cr < 8; cr++) {
        int cd = cr >> 2, ch = (cr >> 1) & 1, cw = cr & 1;
        int di = d0 + cd, hi = h0 + ch, wi = w0 + cw;
        bool valid = (di >= 0) && (di < Din) && (hi >= 0) && (hi < Hin) &&
                     (wi >= 0) && (wi < Win);
        float wt = (cd ? fd : 1.f - fd) * (ch ? fh : 1.f - fh) * (cw ? fw : 1.f - fw);
        wt8[cr] = valid ? wt : 0.f;
        int dic = di < 0 ? 0 : (di > Din - 1 ? Din - 1 : di);
        int hic = hi < 0 ? 0 : (hi > Hin - 1 ? Hin - 1 : hi);
        int wic = wi < 0 ? 0 : (wi > Win - 1 ? Win - 1 : wi);
        idx8[cr] = (dic * Hin + hic) * Win + wic;
    }
#pragma unroll
    for (int cc = 0; cc < 8; cc++) {
        int c = g * 8 + cc;
        size_t base = ncdhw ? ((size_t)(n * C + c)) * Sin
                            : ((size_t)c * NBATCH + n) * Sin;
        const float* bp = in + base;
        float acc = 0.f;
#pragma unroll
        for (int cr = 0; cr < 8; cr++) acc += wt8[cr] * bp[idx8[cr]];
        cols[((size_t)c * 27 + tap) * NS + ns] = acc;
    }
}

// ---------------------------------------------------------------------------
// TF32 tensor-core GEMM: C[M][NS] = A[M][K] * B[K][NS] (+bias).
// 128x128 block tile, BK=16, cp.async double buffer, 8 warps (2x4),
// mma.sync.m16n8k8.tf32. K % 16 == 0, NS % 128 == 0 guaranteed.
// ---------------------------------------------------------------------------
#define GBM 128
#define GBN 128
#define GBK 16
#define AP  20    // As row length in words (BK + 4): conflict-free frag loads
#define BP  136   // Bs row length in words (BN + 8)

__device__ __forceinline__ void cpasync16(float* dst, const float* src, bool pred) {
    uint32_t d = (uint32_t)__cvta_generic_to_shared(dst);
    int sz = pred ? 16 : 0;
    asm volatile("cp.async.cg.shared.global [%0], [%1], 16, %2;\n"
                 :: "r"(d), "l"(src), "r"(sz));
}

__device__ __forceinline__ void mma_tf32(float* c, float a0, float a1, float a2,
                                         float a3, float b0, float b1) {
    asm volatile(
        "mma.sync.aligned.m16n8k8.row.col.f32.tf32.tf32.f32 "
        "{%0,%1,%2,%3}, {%4,%5,%6,%7}, {%8,%9}, {%0,%1,%2,%3};\n"
        : "+f"(c[0]), "+f"(c[1]), "+f"(c[2]), "+f"(c[3])
        : "r"(__float_as_uint(a0)), "r"(__float_as_uint(a1)),
          "r"(__float_as_uint(a2)), "r"(__float_as_uint(a3)),
          "r"(__float_as_uint(b0)), "r"(__float_as_uint(b1)));
}

__global__ __launch_bounds__(256, 2) void gemm_tf32(
    const float* __restrict__ A, const float* __restrict__ B,
    const float* __restrict__ bias, float* __restrict__ C, int M, int K) {
    __shared__ float As[2][GBM * AP];
    __shared__ float Bs[2][GBK * BP];

    int tid  = threadIdx.x;
    int warp = tid >> 5, lane = tid & 31;
    int wm = warp >> 2, wn = warp & 3;      // warps: 2 along M, 4 along N
    int rg = lane >> 2, cg = lane & 3;      // mma groupID / threadID-in-group
    int row0 = blockIdx.x * GBM;
    int col0 = blockIdx.y * GBN;

    // cp.async slot assignment
    int a_m  = tid >> 1;                    // 0..127
    int a_k0 = (tid & 1) * 8;               // two float4 at k0, k0+4
    int b_k  = tid >> 4;                    // 0..15
    int b_n0 = (tid & 15) * 8;              // two float4 at n0, n0+4

    int gmA = row0 + a_m;
    bool aval = gmA < M;
    const float* a_src = A + (size_t)(aval ? gmA : (M - 1)) * K + a_k0;
    const float* b_src = B + (size_t)b_k * NS + col0 + b_n0;

    float acc[4][4][4];
#pragma unroll
    for (int i = 0; i < 4; i++)
#pragma unroll
        for (int j = 0; j < 4; j++)
#pragma unroll
            for (int r = 0; r < 4; r++) acc[i][j][r] = 0.f;

    int T = K / GBK;

    // prologue: tile 0 -> buf 0
    {
        float* ad = &As[0][a_m * AP + a_k0];
        cpasync16(ad, a_src, aval);
        cpasync16(ad + 4, a_src + 4, aval);
        float* bd = &Bs[0][b_k * BP + b_n0];
        cpasync16(bd, b_src, true);
        cpasync16(bd + 4, b_src + 4, true);
        asm volatile("cp.async.commit_group;\n");
    }

    for (int it = 0; it < T; it++) {
        int buf = it & 1;
        if (it + 1 < T) {
            int k0 = (it + 1) * GBK;
            float* ad = &As[buf ^ 1][a_m * AP + a_k0];
            cpasync16(ad, a_src + k0, aval);
            cpasync16(ad + 4, a_src + k0 + 4, aval);
            float* bd = &Bs[buf ^ 1][b_k * BP + b_n0];
            const float* bs = b_src + (size_t)k0 * NS;
            cpasync16(bd, bs, true);
            cpasync16(bd + 4, bs + 4, true);
            asm volatile("cp.async.commit_group;\n");
            asm volatile("cp.async.wait_group 1;\n");
        } else {
            asm volatile("cp.async.wait_group 0;\n");
        }
        __syncthreads();

#pragma unroll
        for (int ks = 0; ks < 2; ks++) {
            int kb = ks * 8;
            float af[4][4];
#pragma unroll
            for (int i = 0; i < 4; i++) {
                int mb = wm * 64 + i * 16;
                af[i][0] = As[buf][(mb + rg) * AP + kb + cg];
                af[i][1] = As[buf][(mb + 8 + rg) * AP + kb + cg];
                af[i][2] = As[buf][(mb + rg) * AP + kb + cg + 4];
                af[i][3] = As[buf][(mb + 8 + rg) * AP + kb + cg + 4];
            }
            float bf[4][2];
#pragma unroll
            for (int j = 0; j < 4; j++) {
                int nb = wn * 32 + j * 8 + rg;
                bf[j][0] = Bs[buf][(kb + cg) * BP + nb];
                bf[j][1] = Bs[buf][(kb + cg + 4) * BP + nb];
            }
#pragma unroll
            for (int i = 0; i < 4; i++)
#pragma unroll
                for (int j = 0; j < 4; j++)
                    mma_tf32(acc[i][j], af[i][0], af[i][1], af[i][2], af[i][3],
                             bf[j][0], bf[j][1]);
        }
        __syncthreads();
    }

    // epilogue
#pragma unroll
    for (int i = 0; i < 4; i++) {
        int gm0 = row0 + wm * 64 + i * 16 + rg;
        int gm1 = gm0 + 8;
#pragma unroll
        for (int j = 0; j < 4; j++) {
            int gc = col0 + wn * 32 + j * 8 + 2 * cg;
            if (gm0 < M) {
                float bv = bias ? bias[gm0] : 0.f;
                float2 v = make_float2(acc[i][j][0] + bv, acc[i][j][1] + bv);
                *(float2*)&C[(size_t)gm0 * NS + gc] = v;
            }
            if (gm1 < M) {
                float bv = bias ? bias[gm1] : 0.f;
                float2 v = make_float2(acc[i][j][2] + bv, acc[i][j][3] + bv);
                *(float2*)&C[(size_t)gm1 * NS + gc] = v;
            }
        }
    }
}

// ---------------------------------------------------------------------------
// BatchNorm statistics: one block per channel, rows of [C][NS].
// ---------------------------------------------------------------------------
__global__ void bn_stats(const float* __restrict__ x, float* __restrict__ mean,
                         float* __restrict__ istd) {
    int c = blockIdx.x;
    const float* row = x + (size_t)c * NS;
    float s = 0.f, s2 = 0.f;
    for (int i = threadIdx.x; i < NS; i += blockDim.x) {
        float v = row[i];
        s += v;
        s2 += v * v;
    }
    __shared__ float sh[256], sh2[256];
    sh[threadIdx.x] = s;
    sh2[threadIdx.x] = s2;
    __syncthreads();
    for (int st = 128; st > 0; st >>= 1) {
        if (threadIdx.x < st) {
            sh[threadIdx.x]  += sh[threadIdx.x + st];
            sh2[threadIdx.x] += sh2[threadIdx.x + st];
        }
        __syncthreads();
    }
    if (threadIdx.x == 0) {
        float m = sh[0] / (float)NS;
        float var = sh2[0] / (float)NS - m * m;
        mean[c] = m;
        istd[c] = rsqrtf(var + 1e-5f);
    }
}

__global__ void bn_apply(float* __restrict__ x, const float* __restrict__ gam,
                         const float* __restrict__ bet,
                         const float* __restrict__ mean,
                         const float* __restrict__ istd, int do_relu) {
    int i = blockIdx.x * blockDim.x + threadIdx.x;
    if (i >= 128 * NS) return;
    int c = i / NS;
    float v = (x[i] - mean[c]) * istd[c] * gam[c] + bet[c];
    if (do_relu) v = fmaxf(v, 0.f);
    x[i] = v;
}

__global__ void final_kernel(const float* __restrict__ raw,
                             const float* __restrict__ gam,
                             const float* __restrict__ bet,
                             const float* __restrict__ mean,
                             const float* __restrict__ istd,
                             const float* __restrict__ res,
                             float* __restrict__ out) {
    int i = blockIdx.x * blockDim.x + threadIdx.x;
    if (i >= 128 * NS) return;
    int n  = i / (128 * S_OUT);
    int co = (i / S_OUT) % 128;
    int s  = i % S_OUT;
    float v = (raw[(size_t)co * NS + n * S_OUT + s] - mean[co]) * istd[co] * gam[co] + bet[co];
    v += res[(size_t)(co & 63) * NS + n * S_OUT + s];
    out[i] = fmaxf(v, 0.f);
}

// ---------------------------------------------------------------------------
// Host launcher
// ---------------------------------------------------------------------------
extern "C" void kernel_launch(void* const* d_in, const int* in_sizes, int n_in,
                              void* d_out, int out_size) {
    (void)in_sizes; (void)n_in; (void)out_size;
    const float* x       = (const float*)d_in[0];
    const float* off1_w  = (const float*)d_in[1];
    const float* off1_b  = (const float*)d_in[2];
    const float* conv1_w = (const float*)d_in[3];
    const float* bn1_g   = (const float*)d_in[4];
    const float* bn1_b   = (const float*)d_in[5];
    const float* off2_w  = (const float*)d_in[6];
    const float* off2_b  = (const float*)d_in[7];
    const float* conv2_w = (const float*)d_in[8];
    const float* bn2_g   = (const float*)d_in[9];
    const float* bn2_b   = (const float*)d_in[10];
    float* out = (float*)d_out;

    float *cols, *off1, *off2, *out1, *out2, *res, *mean, *istd;
    cudaGetSymbolAddress((void**)&cols, g_cols);
    cudaGetSymbolAddress((void**)&off1, g_off1);
    cudaGetSymbolAddress((void**)&off2, g_off2);
    cudaGetSymbolAddress((void**)&out1, g_out1);
    cudaGetSymbolAddress((void**)&out2, g_out2);
    cudaGetSymbolAddress((void**)&res,  g_res);
    cudaGetSymbolAddress((void**)&mean, g_mean);
    cudaGetSymbolAddress((void**)&istd, g_istd);

    const int T = 256;
    long long tot;
    const int NT = NS / GBN;   // 98 column tiles

    // residual = maxpool3d(x)
    maxpool_kernel<<<(64 * NS + T - 1) / T, T>>>(x, res);

    // off1 = conv3d(x, off1_w, off1_b, stride=2)
    tot = (long long)64 * 27 * NS;
    im2col_kernel<<<(unsigned)((tot + T - 1) / T), T>>>(x, cols, 64, 16, 56, 56, 2, 1);
    gemm_tf32<<<dim3((648 + GBM - 1) / GBM, NT), 256>>>(off1_w, cols, off1_b, off1, 648, 1728);

    // out1 = deform_conv3d(x, off1, conv1_w, stride=2)
    tot = (long long)8 * 27 * NS;
    deform_im2col_kernel<<<(unsigned)((tot + T - 1) / T), T>>>(
        x, off1, cols, 64, 8, 16, 56, 56, 2, 1);
    gemm_tf32<<<dim3(1, NT), 256>>>(conv1_w, cols, nullptr, out1, 128, 1728);

    // out1 = relu(bn1(out1))
    bn_stats<<<128, 256>>>(out1, mean, istd);
    bn_apply<<<(128 * NS + T - 1) / T, T>>>(out1, bn1_g, bn1_b, mean, istd, 1);

    // off2 = conv3d(out1, off2_w, off2_b, stride=1)
    tot = (long long)128 * 27 * NS;
    im2col_kernel<<<(unsigned)((tot + T - 1) / T), T>>>(out1, cols, 128, 8, 28, 28, 1, 0);
    gemm_tf32<<<dim3((1296 + GBM - 1) / GBM, NT), 256>>>(off2_w, cols, off2_b, off2, 1296, 3456);

    // out2 = deform_conv3d(out1, off2, conv2_w, stride=1)
    tot = (long long)16 * 27 * NS;
    deform_im2col_kernel<<<(unsigned)((tot + T - 1) / T), T>>>(
        out1, off2, cols, 128, 16, 8, 28, 28, 1, 0);
    gemm_tf32<<<dim3(1, NT), 256>>>(conv2_w, cols, nullptr, out2, 128, 3456);

    // out = relu(bn2(out2) + concat(residual, residual))
    bn_stats<<<128, 256>>>(out2, mean, istd);
    final_kernel<<<(128 * NS + T - 1) / T, T>>>(out2, bn2_g, bn2_b, mean, istd, res, out);
}

// round 5
// speedup vs baseline: 1.1832x; 1.1832x over previous
#include <cuda_runtime.h>
#include <math.h>
#include <stdint.h>

#define NBATCH 2
#define OD 8
#define OH 28
#define OW 28
#define S_OUT 6272
#define NS 12544

__device__ float g_cols[43352064];   // [K][NS], max K=3456
__device__ float g_off1[8128512];    // [648][NS]
__device__ float g_off2[16257024];   // [1296][NS]
__device__ float g_out1[1605632];    // [128][NS]
__device__ float g_out2[1605632];
__device__ float g_res[802816];      // [64][NS]
__device__ float g_mean[128];
__device__ float g_istd[128];

// ---------------- maxpool ----------------
__global__ void maxpool_kernel(const float* __restrict__ x, float* __restrict__ res) {
    int i = blockIdx.x * blockDim.x + threadIdx.x;
    if (i >= 64 * NS) return;
    int ns = i % NS, c = i / NS;
    int n = ns / S_OUT, s = ns % S_OUT;
    int od = s / (OH * OW), oh = (s / OW) % OH, ow = s % OW;
    const float* xp = x + ((size_t)(n * 64 + c)) * 16 * 56 * 56;
    int d0 = od * 2 - 1, h0 = oh * 2 - 1, w0 = ow * 2 - 1;
    int dlo = d0 < 0 ? 0 : d0, dhi = d0 + 2 > 15 ? 15 : d0 + 2;
    int hlo = h0 < 0 ? 0 : h0, hhi = h0 + 2 > 55 ? 55 : h0 + 2;
    int wlo = w0 < 0 ? 0 : w0, whi = w0 + 2 > 55 ? 55 : w0 + 2;
    float m = -INFINITY;
    for (int dd = dlo; dd <= dhi; dd++)
        for (int hh = hlo; hh <= hhi; hh++)
            for (int ww = wlo; ww <= whi; ww++)
                m = fmaxf(m, xp[(dd * 56 + hh) * 56 + ww]);
    res[(size_t)c * NS + ns] = m;
}

// ---------------- im2col -> cols[K][NS] ----------------
__global__ void im2col_kernel(const float* __restrict__ in, float* __restrict__ cols,
                              int C, int Din, int Hin, int Win, int stride, int ncdhw) {
    long long i = (long long)blockIdx.x * blockDim.x + threadIdx.x;
    long long total = (long long)C * 27 * NS;
    if (i >= total) return;
    int ns = (int)(i % NS);
    int ct = (int)(i / NS);
    int tap = ct % 27, c = ct / 27;
    int n = ns / S_OUT, s = ns % S_OUT;
    int od = s / (OH * OW), oh = (s / OW) % OH, ow = s % OW;
    int kd = tap / 9, kh = (tap / 3) % 3, kw = tap % 3;
    int id = od * stride - 1 + kd, ih = oh * stride - 1 + kh, iw = ow * stride - 1 + kw;
    float v = 0.f;
    if (id >= 0 && id < Din && ih >= 0 && ih < Hin && iw >= 0 && iw < Win) {
        size_t Sin = (size_t)Din * Hin * Win;
        size_t base = ncdhw ? ((size_t)(n * C + c)) * Sin : ((size_t)c * NBATCH + n) * Sin;
        v = in[base + ((size_t)id * Hin + ih) * Win + iw];
    }
    cols[(size_t)ct * NS + ns] = v;
}

// ---------------- deformable im2col -> cols[K][NS] ----------------
__global__ void deform_im2col_kernel(const float* __restrict__ in,
                                     const float* __restrict__ off,
                                     float* __restrict__ cols,
                                     int C, int G, int Din, int Hin, int Win,
                                     int stride, int ncdhw) {
    long long i = (long long)blockIdx.x * blockDim.x + threadIdx.x;
    long long total = (long long)G * 27 * NS;
    if (i >= total) return;
    int ns = (int)(i % NS);
    int gt = (int)(i / NS);
    int tap = gt % 27, g = gt / 27;
    int n = ns / S_OUT, s = ns % S_OUT;
    int od = s / (OH * OW), oh = (s / OW) % OH, ow = s % OW;
    int kd = tap / 9, kh = (tap / 3) % 3, kw = tap % 3;

    size_t ob = ((size_t)(g * 3) * 27 + tap) * NS + ns;
    float pd = off[ob]                   + (float)(od * stride - 1 + kd);
    float ph = off[ob + (size_t)27 * NS] + (float)(oh * stride - 1 + kh);
    float pw = off[ob + (size_t)54 * NS] + (float)(ow * stride - 1 + kw);

    float d0f = floorf(pd), h0f = floorf(ph), w0f = floorf(pw);
    int d0 = (int)d0f, h0 = (int)h0f, w0 = (int)w0f;
    float fd = pd - d0f, fh = ph - h0f, fw = pw - w0f;

    float wt8[8]; int idx8[8];
    int Sin = Din * Hin * Win;
#pragma unroll
    for (int cr = 0; cr < 8; cr++) {
        int cd = cr >> 2, ch = (cr >> 1) & 1, cw = cr & 1;
        int di = d0 + cd, hi = h0 + ch, wi = w0 + cw;
        bool valid = (di >= 0) && (di < Din) && (hi >= 0) && (hi < Hin) &&
                     (wi >= 0) && (wi < Win);
        float wt = (cd ? fd : 1.f - fd) * (ch ? fh : 1.f - fh) * (cw ? fw : 1.f - fw);
        wt8[cr] = valid ? wt : 0.f;
        int dic = di < 0 ? 0 : (di > Din - 1 ? Din - 1 : di);
        int hic = hi < 0 ? 0 : (hi > Hin - 1 ? Hin - 1 : hi);
        int wic = wi < 0 ? 0 : (wi > Win - 1 ? Win - 1 : wi);
        idx8[cr] = (dic * Hin + hic) * Win + wic;
    }
#pragma unroll
    for (int cc = 0; cc < 8; cc++) {
        int c = g * 8 + cc;
        size_t base = ncdhw ? ((size_t)(n * C + c)) * Sin : ((size_t)c * NBATCH + n) * Sin;
        const float* bp = in + base;
        float acc = 0.f;
#pragma unroll
        for (int cr = 0; cr < 8; cr++) acc += wt8[cr] * bp[idx8[cr]];
        cols[((size_t)c * 27 + tap) * NS + ns] = acc;
    }
}

// ---------------------------------------------------------------------------
// TF32 mma.sync GEMM, 3-stage cp.async, one sync per k-tile.
// C[M][NS] = A[M][K] * B[K][NS] (+bias).  BM=128, BN in {128,256}, BK=16.
// 8 warps as 2x4; warp tile 64 x (BN/4); m16n8k8 fragments.
// ---------------------------------------------------------------------------
#define BKT 16
#define APD 20   // As row pitch (words)

__device__ __forceinline__ void cpasync16(float* dst, const float* src, bool pred) {
    uint32_t d = (uint32_t)__cvta_generic_to_shared(dst);
    int sz = pred ? 16 : 0;
    asm volatile("cp.async.cg.shared.global [%0], [%1], 16, %2;\n"
                 :: "r"(d), "l"(src), "r"(sz));
}
__device__ __forceinline__ void mma_tf32(float* c, float a0, float a1, float a2,
                                         float a3, float b0, float b1) {
    asm volatile(
        "mma.sync.aligned.m16n8k8.row.col.f32.tf32.tf32.f32 "
        "{%0,%1,%2,%3}, {%4,%5,%6,%7}, {%8,%9}, {%0,%1,%2,%3};\n"
        : "+f"(c[0]), "+f"(c[1]), "+f"(c[2]), "+f"(c[3])
        : "r"(__float_as_uint(a0)), "r"(__float_as_uint(a1)),
          "r"(__float_as_uint(a2)), "r"(__float_as_uint(a3)),
          "r"(__float_as_uint(b0)), "r"(__float_as_uint(b1)));
}

template <int BN>
__global__ __launch_bounds__(256) void gemm_v2(
    const float* __restrict__ A, const float* __restrict__ B,
    const float* __restrict__ bias, float* __restrict__ C, int M, int K) {
    constexpr int BM = 128;
    constexpr int BP = BN + 8;
    constexpr int WN = BN / 4;          // warp tile width
    constexpr int NT = WN / 8;          // n fragments per warp
    constexpr int ABYT = BM * APD * 4;  // A stage bytes
    constexpr int BBYT = BKT * BP * 4;  // B stage bytes
    constexpr int ASL = (BM * BKT) / 4 / 256;  // A float4 slots per thread (2)
    constexpr int BSL = (BKT * BN) / 4 / 256;  // B float4 slots per thread

    extern __shared__ char smraw[];
    float* Asm = (float*)smraw;                  // 3 stages
    float* Bsm = (float*)(smraw + 3 * ABYT);     // 3 stages

    int tid = threadIdx.x;
    int warp = tid >> 5, lane = tid & 31;
    int wm = warp >> 2, wn = warp & 3;
    int rg = lane >> 2, cg = lane & 3;
    int row0 = blockIdx.x * BM;
    int col0 = blockIdx.y * BN;
    int T = K / BKT;

    // copy-slot geometry
    int am[ASL], akq[ASL]; bool aok[ASL];
    const float* asrc[ASL];
#pragma unroll
    for (int u = 0; u < ASL; u++) {
        int slot = u * 256 + tid;
        am[u] = slot >> 2; akq[u] = slot & 3;
        int gm = row0 + am[u];
        aok[u] = gm < M;
        asrc[u] = A + (size_t)(aok[u] ? gm : 0) * K + akq[u] * 4;
    }
    int bk[BSL], bnq[BSL];
    const float* bsrc[BSL];
#pragma unroll
    for (int u = 0; u < BSL; u++) {
        int slot = u * 256 + tid;
        bk[u] = slot / (BN / 4); bnq[u] = slot % (BN / 4);
        bsrc[u] = B + (size_t)bk[u] * NS + col0 + bnq[u] * 4;
    }

    float acc[4][NT][4];
#pragma unroll
    for (int i = 0; i < 4; i++)
#pragma unroll
        for (int j = 0; j < NT; j++)
#pragma unroll
            for (int r = 0; r < 4; r++) acc[i][j][r] = 0.f;

    // prologue: tiles 0,1 -> stages 0,1
#pragma unroll
    for (int t = 0; t < 2; t++) {
#pragma unroll
        for (int u = 0; u < ASL; u++)
            cpasync16(&Asm[t * BM * APD + am[u] * APD + akq[u] * 4],
                      asrc[u] + t * BKT, aok[u]);
#pragma unroll
        for (int u = 0; u < BSL; u++)
            cpasync16(&Bsm[t * BKT * BP + bk[u] * BP + bnq[u] * 4],
                      bsrc[u] + (size_t)(t * BKT) * NS, true);
        asm volatile("cp.async.commit_group;\n");
    }

    for (int t = 0; t < T; t++) {
        asm volatile("cp.async.wait_group 1;\n");
        __syncthreads();
        int st = t % 3;
        const float* As = Asm + st * BM * APD;
        const float* Bst = Bsm + st * BKT * BP;
#pragma unroll
        for (int ks = 0; ks < 2; ks++) {
            int kb = ks * 8;
            float af[4][4];
#pragma unroll
            for (int i = 0; i < 4; i++) {
                int mb = wm * 64 + i * 16;
                af[i][0] = As[(mb + rg) * APD + kb + cg];
                af[i][1] = As[(mb + 8 + rg) * APD + kb + cg];
                af[i][2] = As[(mb + rg) * APD + kb + cg + 4];
                af[i][3] = As[(mb + 8 + rg) * APD + kb + cg + 4];
            }
            float bf[NT][2];
#pragma unroll
            for (int j = 0; j < NT; j++) {
                int nb = wn * WN + j * 8 + rg;
                bf[j][0] = Bst[(kb + cg) * BP + nb];
                bf[j][1] = Bst[(kb + cg + 4) * BP + nb];
            }
#pragma unroll
            for (int i = 0; i < 4; i++)
#pragma unroll
                for (int j = 0; j < NT; j++)
                    mma_tf32(acc[i][j], af[i][0], af[i][1], af[i][2], af[i][3],
                             bf[j][0], bf[j][1]);
        }
        // issue tile t+2 into stage (t+2)%3
        int tn = t + 2;
        if (tn < T) {
            int sn = tn % 3;
            int k0 = tn * BKT;
#pragma unroll
            for (int u = 0; u < ASL; u++)
                cpasync16(&Asm[sn * BM * APD + am[u] * APD + akq[u] * 4],
                          asrc[u] + k0, aok[u]);
#pragma unroll
            for (int u = 0; u < BSL; u++)
                cpasync16(&Bsm[sn * BKT * BP + bk[u] * BP + bnq[u] * 4],
                          bsrc[u] + (size_t)k0 * NS, true);
        }
        asm volatile("cp.async.commit_group;\n");
    }

    // epilogue
#pragma unroll
    for (int i = 0; i < 4; i++) {
        int gm0 = row0 + wm * 64 + i * 16 + rg;
        int gm1 = gm0 + 8;
        float bv0 = (bias && gm0 < M) ? bias[gm0] : 0.f;
        float bv1 = (bias && gm1 < M) ? bias[gm1] : 0.f;
#pragma unroll
        for (int j = 0; j < NT; j++) {
            int gc = col0 + wn * WN + j * 8 + 2 * cg;
            if (gm0 < M)
                *(float2*)&C[(size_t)gm0 * NS + gc] =
                    make_float2(acc[i][j][0] + bv0, acc[i][j][1] + bv0);
            if (gm1 < M)
                *(float2*)&C[(size_t)gm1 * NS + gc] =
                    make_float2(acc[i][j][2] + bv1, acc[i][j][3] + bv1);
        }
    }
}

#define SMEM_G256 (3 * (128 * APD * 4 + BKT * (256 + 8) * 4))   // 81408
#define SMEM_G128 (3 * (128 * APD * 4 + BKT * (128 + 8) * 4))   // 56832

// ---------------- BN / final ----------------
__global__ void bn_stats(const float* __restrict__ x, float* __restrict__ mean,
                         float* __restrict__ istd) {
    int c = blockIdx.x;
    const float* row = x + (size_t)c * NS;
    float s = 0.f, s2 = 0.f;
    for (int i = threadIdx.x; i < NS; i += blockDim.x) {
        float v = row[i];
        s += v; s2 += v * v;
    }
    __shared__ float sh[256], sh2[256];
    sh[threadIdx.x] = s; sh2[threadIdx.x] = s2;
    __syncthreads();
    for (int st = 128; st > 0; st >>= 1) {
        if (threadIdx.x < st) {
            sh[threadIdx.x] += sh[threadIdx.x + st];
            sh2[threadIdx.x] += sh2[threadIdx.x + st];
        }
        __syncthreads();
    }
    if (threadIdx.x == 0) {
        float m = sh[0] / (float)NS;
        float var = sh2[0] / (float)NS - m * m;
        mean[c] = m;
        istd[c] = rsqrtf(var + 1e-5f);
    }
}

__global__ void bn_apply(float* __restrict__ x, const float* __restrict__ gam,
                         const float* __restrict__ bet, const float* __restrict__ mean,
                         const float* __restrict__ istd, int do_relu) {
    int i = blockIdx.x * blockDim.x + threadIdx.x;
    if (i >= 128 * NS) return;
    int c = i / NS;
    float v = (x[i] - mean[c]) * istd[c] * gam[c] + bet[c];
    if (do_relu) v = fmaxf(v, 0.f);
    x[i] = v;
}

__global__ void final_kernel(const float* __restrict__ raw, const float* __restrict__ gam,
                             const float* __restrict__ bet, const float* __restrict__ mean,
                             const float* __restrict__ istd, const float* __restrict__ res,
                             float* __restrict__ out) {
    int i = blockIdx.x * blockDim.x + threadIdx.x;
    if (i >= 128 * NS) return;
    int n = i / (128 * S_OUT);
    int co = (i / S_OUT) % 128;
    int s = i % S_OUT;
    float v = (raw[(size_t)co * NS + n * S_OUT + s] - mean[co]) * istd[co] * gam[co] + bet[co];
    v += res[(size_t)(co & 63) * NS + n * S_OUT + s];
    out[i] = fmaxf(v, 0.f);
}

// ---------------- host ----------------
extern "C" void kernel_launch(void* const* d_in, const int* in_sizes, int n_in,
                              void* d_out, int out_size) {
    (void)in_sizes; (void)n_in; (void)out_size;
    const float* x       = (const float*)d_in[0];
    const float* off1_w  = (const float*)d_in[1];
    const float* off1_b  = (const float*)d_in[2];
    const float* conv1_w = (const float*)d_in[3];
    const float* bn1_g   = (const float*)d_in[4];
    const float* bn1_b   = (const float*)d_in[5];
    const float* off2_w  = (const float*)d_in[6];
    const float* off2_b  = (const float*)d_in[7];
    const float* conv2_w = (const float*)d_in[8];
    const float* bn2_g   = (const float*)d_in[9];
    const float* bn2_b   = (const float*)d_in[10];
    float* out = (float*)d_out;

    float *cols, *off1, *off2, *out1, *out2, *res, *mean, *istd;
    cudaGetSymbolAddress((void**)&cols, g_cols);
    cudaGetSymbolAddress((void**)&off1, g_off1);
    cudaGetSymbolAddress((void**)&off2, g_off2);
    cudaGetSymbolAddress((void**)&out1, g_out1);
    cudaGetSymbolAddress((void**)&out2, g_out2);
    cudaGetSymbolAddress((void**)&res,  g_res);
    cudaGetSymbolAddress((void**)&mean, g_mean);
    cudaGetSymbolAddress((void**)&istd, g_istd);

    static int attr_done = 0;
    if (!attr_done) {
        cudaFuncSetAttribute(gemm_v2<256>, cudaFuncAttributeMaxDynamicSharedMemorySize, SMEM_G256);
        cudaFuncSetAttribute(gemm_v2<128>, cudaFuncAttributeMaxDynamicSharedMemorySize, SMEM_G128);
        attr_done = 1;
    }

    const int T = 256;
    long long tot;

    maxpool_kernel<<<(64 * NS + T - 1) / T, T>>>(x, res);

    // off1 = conv3d(x, stride=2): M=648, K=1728
    tot = (long long)64 * 27 * NS;
    im2col_kernel<<<(unsigned)((tot + T - 1) / T), T>>>(x, cols, 64, 16, 56, 56, 2, 1);
    gemm_v2<256><<<dim3(6, NS / 256), 256, SMEM_G256>>>(off1_w, cols, off1_b, off1, 648, 1728);

    // out1 = deform_conv3d(x, off1, stride=2): M=128, K=1728
    tot = (long long)8 * 27 * NS;
    deform_im2col_kernel<<<(unsigned)((tot + T - 1) / T), T>>>(
        x, off1, cols, 64, 8, 16, 56, 56, 2, 1);
    gemm_v2<128><<<dim3(1, NS / 128), 256, SMEM_G128>>>(conv1_w, cols, nullptr, out1, 128, 1728);

    bn_stats<<<128, 256>>>(out1, mean, istd);
    bn_apply<<<(128 * NS + T - 1) / T, T>>>(out1, bn1_g, bn1_b, mean, istd, 1);

    // off2 = conv3d(out1, stride=1): M=1296, K=3456
    tot = (long long)128 * 27 * NS;
    im2col_kernel<<<(unsigned)((tot + T - 1) / T), T>>>(out1, cols, 128, 8, 28, 28, 1, 0);
    gemm_v2<256><<<dim3(11, NS / 256), 256, SMEM_G256>>>(off2_w, cols, off2_b, off2, 1296, 3456);

    // out2 = deform_conv3d(out1, off2, stride=1): M=128, K=3456
    tot = (long long)16 * 27 * NS;
    deform_im2col_kernel<<<(unsigned)((tot + T - 1) / T), T>>>(
        out1, off2, cols, 128, 16, 8, 28, 28, 1, 0);
    gemm_v2<128><<<dim3(1, NS / 128), 256, SMEM_G128>>>(conv2_w, cols, nullptr, out2, 128, 3456);

    bn_stats<<<128, 256>>>(out2, mean, istd);
    final_kernel<<<(128 * NS + T - 1) / T, T>>>(out2, bn2_g, bn2_b, mean, istd, res, out);
}

// round 6
// speedup vs baseline: 1.3874x; 1.1726x over previous
#include <cuda_runtime.h>
#include <cuda_fp16.h>
#include <math.h>
#include <stdint.h>

#define NBATCH 2
#define OD 8
#define OH 28
#define OW 28
#define S_OUT 6272
#define NS 12544

__device__ __half g_cols[43352064];  // [ns][K], max K=3456
__device__ __half g_wh[6262272];     // all four weight sets, half
__device__ float g_off1[8128512];    // [648][NS]
__device__ float g_off2[16257024];   // [1296][NS]
__device__ float g_out1[1605632];    // [128][NS]
__device__ float g_out2[1605632];
__device__ float g_res[802816];      // [64][NS]
__device__ float g_mean[128];
__device__ float g_istd[128];

// weight offsets inside g_wh
#define WH_OFF1 0
#define WH_CV1  1119744
#define WH_OFF2 1340928
#define WH_CV2  5819904

// ---------------- fp32 -> fp16 ----------------
__global__ void f2h_kernel(const float* __restrict__ in, __half* __restrict__ out, int n) {
    int i = blockIdx.x * blockDim.x + threadIdx.x;
    if (i < n) out[i] = __float2half(in[i]);
}

// ---------------- maxpool ----------------
__global__ void maxpool_kernel(const float* __restrict__ x, float* __restrict__ res) {
    int i = blockIdx.x * blockDim.x + threadIdx.x;
    if (i >= 64 * NS) return;
    int ns = i % NS, c = i / NS;
    int n = ns / S_OUT, s = ns % S_OUT;
    int od = s / (OH * OW), oh = (s / OW) % OH, ow = s % OW;
    const float* xp = x + ((size_t)(n * 64 + c)) * 16 * 56 * 56;
    int d0 = od * 2 - 1, h0 = oh * 2 - 1, w0 = ow * 2 - 1;
    int dlo = d0 < 0 ? 0 : d0, dhi = d0 + 2 > 15 ? 15 : d0 + 2;
    int hlo = h0 < 0 ? 0 : h0, hhi = h0 + 2 > 55 ? 55 : h0 + 2;
    int wlo = w0 < 0 ? 0 : w0, whi = w0 + 2 > 55 ? 55 : w0 + 2;
    float m = -INFINITY;
    for (int dd = dlo; dd <= dhi; dd++)
        for (int hh = hlo; hh <= hhi; hh++)
            for (int ww = wlo; ww <= whi; ww++)
                m = fmaxf(m, xp[(dd * 56 + hh) * 56 + ww]);
    res[(size_t)c * NS + ns] = m;
}

// ---------------- im2col -> cols[ns][K] (half) ----------------
__global__ void im2col_T(const float* __restrict__ in, __half* __restrict__ cols,
                         int C, int Din, int Hin, int Win, int stride, int ncdhw) {
    int K = C * 27;
    long long i = (long long)blockIdx.x * blockDim.x + threadIdx.x;
    if (i >= (long long)NS * K) return;
    int k = (int)(i % K), ns = (int)(i / K);
    int c = k / 27, tap = k % 27;
    int n = ns / S_OUT, s = ns % S_OUT;
    int od = s / (OH * OW), oh = (s / OW) % OH, ow = s % OW;
    int kd = tap / 9, kh = (tap / 3) % 3, kw = tap % 3;
    int id = od * stride - 1 + kd, ih = oh * stride - 1 + kh, iw = ow * stride - 1 + kw;
    float v = 0.f;
    if (id >= 0 && id < Din && ih >= 0 && ih < Hin && iw >= 0 && iw < Win) {
        size_t Sin = (size_t)Din * Hin * Win;
        size_t base = ncdhw ? ((size_t)(n * C + c)) * Sin : ((size_t)c * NBATCH + n) * Sin;
        v = in[base + ((size_t)id * Hin + ih) * Win + iw];
    }
    cols[i] = __float2half(v);
}

// ---------------- deformable im2col -> cols[ns][K] (half), smem staged -------
// Block: 864 threads = 27 warps (warp = tap, lane = ns). Grid (NS/32, G).
__global__ __launch_bounds__(864) void deform_T(
    const float* __restrict__ in, const float* __restrict__ off,
    __half* __restrict__ cols, int C, int G, int Din, int Hin, int Win,
    int stride, int ncdhw) {
    __shared__ float sbuf[216 * 33];
    int K = C * 27;
    int tid = threadIdx.x;
    int nsl = tid & 31, tap = tid >> 5;
    int nsb = blockIdx.x * 32, g = blockIdx.y;
    int ns = nsb + nsl;
    int n = ns / S_OUT, s = ns % S_OUT;
    int od = s / (OH * OW), oh = (s / OW) % OH, ow = s % OW;
    int kd = tap / 9, kh = (tap / 3) % 3, kw = tap % 3;

    size_t ob = ((size_t)(g * 3) * 27 + tap) * NS + ns;
    float pd = off[ob]                   + (float)(od * stride - 1 + kd);
    float ph = off[ob + (size_t)27 * NS] + (float)(oh * stride - 1 + kh);
    float pw = off[ob + (size_t)54 * NS] + (float)(ow * stride - 1 + kw);
    float d0f = floorf(pd), h0f = floorf(ph), w0f = floorf(pw);
    int d0 = (int)d0f, h0 = (int)h0f, w0 = (int)w0f;
    float fd = pd - d0f, fh = ph - h0f, fw = pw - w0f;

    float wt8[8]; int idx8[8];
    int Sin = Din * Hin * Win;
#pragma unroll
    for (int cr = 0; cr < 8; cr++) {
        int cd = cr >> 2, ch = (cr >> 1) & 1, cw = cr & 1;
        int di = d0 + cd, hi = h0 + ch, wi = w0 + cw;
        bool valid = (di >= 0) && (di < Din) && (hi >= 0) && (hi < Hin) &&
                     (wi >= 0) && (wi < Win);
        float wt = (cd ? fd : 1.f - fd) * (ch ? fh : 1.f - fh) * (cw ? fw : 1.f - fw);
        wt8[cr] = valid ? wt : 0.f;
        int dic = di < 0 ? 0 : (di > Din - 1 ? Din - 1 : di);
        int hic = hi < 0 ? 0 : (hi > Hin - 1 ? Hin - 1 : hi);
        int wic = wi < 0 ? 0 : (wi > Win - 1 ? Win - 1 : wi);
        idx8[cr] = (dic * Hin + hic) * Win + wic;
    }
#pragma unroll
    for (int cc = 0; cc < 8; cc++) {
        int c = g * 8 + cc;
        size_t base = ncdhw ? ((size_t)(n * C + c)) * Sin : ((size_t)c * NBATCH + n) * Sin;
        const float* bp = in + base;
        float acc = 0.f;
#pragma unroll
        for (int cr = 0; cr < 8; cr++) acc += wt8[cr] * bp[idx8[cr]];
        sbuf[(cc * 27 + tap) * 33 + nsl] = acc;
    }
    __syncthreads();
#pragma unroll
    for (int it = 0; it < 8; it++) {
        int j = it * 864 + tid;
        int nsi = j / 216, kk = j % 216;
        cols[(size_t)(nsb + nsi) * K + g * 216 + kk] = __float2half(sbuf[kk * 33 + nsi]);
    }
}

// ---------------------------------------------------------------------------
// FP16 mma.sync GEMM: C[M][NS] = A[M][K]*B^T (+bias), A=[M][K] half,
// B=cols[ns][K] half (col-major K x NS).  BM=128, BN in {128,256}, BK=32.
// 3-stage cp.async, one __syncthreads per k-tile; 8 warps 2x4, warp 64x(BN/4).
// ---------------------------------------------------------------------------
#define HBK 32
#define HPH 40   // row pitch in halves (32 + 8)

__device__ __forceinline__ void cpasync16h(__half* dst, const __half* src, bool pred) {
    uint32_t d = (uint32_t)__cvta_generic_to_shared(dst);
    int sz = pred ? 16 : 0;
    asm volatile("cp.async.cg.shared.global [%0], [%1], 16, %2;\n"
                 :: "r"(d), "l"(src), "r"(sz));
}
__device__ __forceinline__ void mma_f16(float* c, uint32_t a0, uint32_t a1,
                                        uint32_t a2, uint32_t a3,
                                        uint32_t b0, uint32_t b1) {
    asm volatile(
        "mma.sync.aligned.m16n8k16.row.col.f32.f16.f16.f32 "
        "{%0,%1,%2,%3}, {%4,%5,%6,%7}, {%8,%9}, {%0,%1,%2,%3};\n"
        : "+f"(c[0]), "+f"(c[1]), "+f"(c[2]), "+f"(c[3])
        : "r"(a0), "r"(a1), "r"(a2), "r"(a3), "r"(b0), "r"(b1));
}

template <int BN>
__global__ __launch_bounds__(256) void gemm_h(
    const __half* __restrict__ A, const __half* __restrict__ B,
    const float* __restrict__ bias, float* __restrict__ C, int M, int K) {
    constexpr int BM = 128;
    constexpr int WN = BN / 4;
    constexpr int NT = WN / 8;                  // n frags per warp
    constexpr int AH = BM * HPH;                // A stage halves
    constexpr int BH = BN * HPH;                // B stage halves
    constexpr int ASL = BM * HBK / 8 / 256;     // 2
    constexpr int BSL = BN * HBK / 8 / 256;     // 2 or 4

    extern __shared__ __half smh[];
    __half* Asm = smh;
    __half* Bsm = smh + 3 * AH;

    int tid = threadIdx.x;
    int warp = tid >> 5, lane = tid & 31;
    int wm = warp >> 2, wn = warp & 3;
    int rg = lane >> 2, cg = lane & 3;
    int row0 = blockIdx.x * BM;
    int col0 = blockIdx.y * BN;
    int T = K / HBK;

    // copy-slot geometry: 8-half (16B) chunks, 4 chunks per row of 32 halves
    int am[ASL], akq[ASL]; bool aok[ASL];
    const __half* asrc[ASL];
#pragma unroll
    for (int u = 0; u < ASL; u++) {
        int slot = u * 256 + tid;
        am[u] = slot >> 2; akq[u] = slot & 3;
        int gm = row0 + am[u];
        aok[u] = gm < M;
        asrc[u] = A + (size_t)(aok[u] ? gm : 0) * K + akq[u] * 8;
    }
    int bn_[BSL], bkq[BSL];
    const __half* bsrc[BSL];
#pragma unroll
    for (int u = 0; u < BSL; u++) {
        int slot = u * 256 + tid;
        bn_[u] = slot >> 2; bkq[u] = slot & 3;
        bsrc[u] = B + (size_t)(col0 + bn_[u]) * K + bkq[u] * 8;
    }

    float acc[4][NT][4];
#pragma unroll
    for (int i = 0; i < 4; i++)
#pragma unroll
        for (int j = 0; j < NT; j++)
#pragma unroll
            for (int r = 0; r < 4; r++) acc[i][j][r] = 0.f;

    // prologue: tiles 0,1 -> stages 0,1
#pragma unroll
    for (int t = 0; t < 2; t++) {
#pragma unroll
        for (int u = 0; u < ASL; u++)
            cpasync16h(&Asm[t * AH + am[u] * HPH + akq[u] * 8], asrc[u] + t * HBK, aok[u]);
#pragma unroll
        for (int u = 0; u < BSL; u++)
            cpasync16h(&Bsm[t * BH + bn_[u] * HPH + bkq[u] * 8], bsrc[u] + t * HBK, true);
        asm volatile("cp.async.commit_group;\n");
    }

    for (int t = 0; t < T; t++) {
        asm volatile("cp.async.wait_group 1;\n");
        __syncthreads();
        int st = t % 3;
        const uint32_t* As32 = (const uint32_t*)(Asm + st * AH);
        const uint32_t* Bs32 = (const uint32_t*)(Bsm + st * BH);
#pragma unroll
        for (int ks = 0; ks < 2; ks++) {
            int kw = ks * 8 + cg;     // word offset within row (HPH/2=20 words)
            uint32_t af[4][4];
#pragma unroll
            for (int i = 0; i < 4; i++) {
                int mb = wm * 64 + i * 16;
                af[i][0] = As32[(mb + rg) * 20 + kw];
                af[i][1] = As32[(mb + 8 + rg) * 20 + kw];
                af[i][2] = As32[(mb + rg) * 20 + kw + 4];
                af[i][3] = As32[(mb + 8 + rg) * 20 + kw + 4];
            }
            uint32_t bf[NT][2];
#pragma unroll
            for (int j = 0; j < NT; j++) {
                int nb = wn * WN + j * 8 + rg;
                bf[j][0] = Bs32[nb * 20 + kw];
                bf[j][1] = Bs32[nb * 20 + kw + 4];
            }
#pragma unroll
            for (int i = 0; i < 4; i++)
#pragma unroll
                for (int j = 0; j < NT; j++)
                    mma_f16(acc[i][j], af[i][0], af[i][1], af[i][2], af[i][3],
                            bf[j][0], bf[j][1]);
        }
        int tn = t + 2;
        if (tn < T) {
            int sn = tn % 3;
            int k0 = tn * HBK;
#pragma unroll
            for (int u = 0; u < ASL; u++)
                cpasync16h(&Asm[sn * AH + am[u] * HPH + akq[u] * 8], asrc[u] + k0, aok[u]);
#pragma unroll
            for (int u = 0; u < BSL; u++)
                cpasync16h(&Bsm[sn * BH + bn_[u] * HPH + bkq[u] * 8], bsrc[u] + k0, true);
        }
        asm volatile("cp.async.commit_group;\n");
    }

    // epilogue
#pragma unroll
    for (int i = 0; i < 4; i++) {
        int gm0 = row0 + wm * 64 + i * 16 + rg;
        int gm1 = gm0 + 8;
        float bv0 = (bias && gm0 < M) ? bias[gm0] : 0.f;
        float bv1 = (bias && gm1 < M) ? bias[gm1] : 0.f;
#pragma unroll
        for (int j = 0; j < NT; j++) {
            int gc = col0 + wn * WN + j * 8 + 2 * cg;
            if (gm0 < M)
                *(float2*)&C[(size_t)gm0 * NS + gc] =
                    make_float2(acc[i][j][0] + bv0, acc[i][j][1] + bv0);
            if (gm1 < M)
                *(float2*)&C[(size_t)gm1 * NS + gc] =
                    make_float2(acc[i][j][2] + bv1, acc[i][j][3] + bv1);
        }
    }
}

#define SMEMH256 (3 * (128 * HPH + 256 * HPH) * 2)   // 92160
#define SMEMH128 (3 * (128 * HPH + 128 * HPH) * 2)   // 61440

// ---------------- BN / final ----------------
__global__ void bn_stats(const float* __restrict__ x, float* __restrict__ mean,
                         float* __restrict__ istd) {
    int c = blockIdx.x;
    const float* row = x + (size_t)c * NS;
    float s = 0.f, s2 = 0.f;
    for (int i = threadIdx.x; i < NS; i += blockDim.x) {
        float v = row[i];
        s += v; s2 += v * v;
    }
    __shared__ float sh[256], sh2[256];
    sh[threadIdx.x] = s; sh2[threadIdx.x] = s2;
    __syncthreads();
    for (int st = 128; st > 0; st >>= 1) {
        if (threadIdx.x < st) {
            sh[threadIdx.x] += sh[threadIdx.x + st];
            sh2[threadIdx.x] += sh2[threadIdx.x + st];
        }
        __syncthreads();
    }
    if (threadIdx.x == 0) {
        float m = sh[0] / (float)NS;
        float var = sh2[0] / (float)NS - m * m;
        mean[c] = m;
        istd[c] = rsqrtf(var + 1e-5f);
    }
}

__global__ void bn_apply(float* __restrict__ x, const float* __restrict__ gam,
                         const float* __restrict__ bet, const float* __restrict__ mean,
                         const float* __restrict__ istd, int do_relu) {
    int i = blockIdx.x * blockDim.x + threadIdx.x;
    if (i >= 128 * NS) return;
    int c = i / NS;
    float v = (x[i] - mean[c]) * istd[c] * gam[c] + bet[c];
    if (do_relu) v = fmaxf(v, 0.f);
    x[i] = v;
}

__global__ void final_kernel(const float* __restrict__ raw, const float* __restrict__ gam,
                             const float* __restrict__ bet, const float* __restrict__ mean,
                             const float* __restrict__ istd, const float* __restrict__ res,
                             float* __restrict__ out) {
    int i = blockIdx.x * blockDim.x + threadIdx.x;
    if (i >= 128 * NS) return;
    int n = i / (128 * S_OUT);
    int co = (i / S_OUT) % 128;
    int s = i % S_OUT;
    float v = (raw[(size_t)co * NS + n * S_OUT + s] - mean[co]) * istd[co] * gam[co] + bet[co];
    v += res[(size_t)(co & 63) * NS + n * S_OUT + s];
    out[i] = fmaxf(v, 0.f);
}

// ---------------- host ----------------
extern "C" void kernel_launch(void* const* d_in, const int* in_sizes, int n_in,
                              void* d_out, int out_size) {
    (void)in_sizes; (void)n_in; (void)out_size;
    const float* x       = (const float*)d_in[0];
    const float* off1_w  = (const float*)d_in[1];
    const float* off1_b  = (const float*)d_in[2];
    const float* conv1_w = (const float*)d_in[3];
    const float* bn1_g   = (const float*)d_in[4];
    const float* bn1_b   = (const float*)d_in[5];
    const float* off2_w  = (const float*)d_in[6];
    const float* off2_b  = (const float*)d_in[7];
    const float* conv2_w = (const float*)d_in[8];
    const float* bn2_g   = (const float*)d_in[9];
    const float* bn2_b   = (const float*)d_in[10];
    float* out = (float*)d_out;

    __half *cols, *wh;
    float *off1, *off2, *out1, *out2, *res, *mean, *istd;
    cudaGetSymbolAddress((void**)&cols, g_cols);
    cudaGetSymbolAddress((void**)&wh,   g_wh);
    cudaGetSymbolAddress((void**)&off1, g_off1);
    cudaGetSymbolAddress((void**)&off2, g_off2);
    cudaGetSymbolAddress((void**)&out1, g_out1);
    cudaGetSymbolAddress((void**)&out2, g_out2);
    cudaGetSymbolAddress((void**)&res,  g_res);
    cudaGetSymbolAddress((void**)&mean, g_mean);
    cudaGetSymbolAddress((void**)&istd, g_istd);

    static int attr_done = 0;
    if (!attr_done) {
        cudaFuncSetAttribute(gemm_h<256>, cudaFuncAttributeMaxDynamicSharedMemorySize, SMEMH256);
        cudaFuncSetAttribute(gemm_h<128>, cudaFuncAttributeMaxDynamicSharedMemorySize, SMEMH128);
        attr_done = 1;
    }

    const int T = 256;
    long long tot;

    // convert all weights to half
    f2h_kernel<<<(1119744 + T - 1) / T, T>>>(off1_w,  wh + WH_OFF1, 1119744);
    f2h_kernel<<<(221184  + T - 1) / T, T>>>(conv1_w, wh + WH_CV1,  221184);
    f2h_kernel<<<(4478976 + T - 1) / T, T>>>(off2_w,  wh + WH_OFF2, 4478976);
    f2h_kernel<<<(442368  + T - 1) / T, T>>>(conv2_w, wh + WH_CV2,  442368);

    maxpool_kernel<<<(64 * NS + T - 1) / T, T>>>(x, res);

    // off1 = conv3d(x, stride=2): M=648, K=1728
    tot = (long long)NS * 1728;
    im2col_T<<<(unsigned)((tot + T - 1) / T), T>>>(x, cols, 64, 16, 56, 56, 2, 1);
    gemm_h<256><<<dim3(6, NS / 256), 256, SMEMH256>>>(wh + WH_OFF1, cols, off1_b, off1, 648, 1728);

    // out1 = deform_conv3d(x, off1, stride=2): M=128, K=1728
    deform_T<<<dim3(NS / 32, 8), 864>>>(x, off1, cols, 64, 8, 16, 56, 56, 2, 1);
    gemm_h<128><<<dim3(1, NS / 128), 256, SMEMH128>>>(wh + WH_CV1, cols, nullptr, out1, 128, 1728);

    bn_stats<<<128, 256>>>(out1, mean, istd);
    bn_apply<<<(128 * NS + T - 1) / T, T>>>(out1, bn1_g, bn1_b, mean, istd, 1);

    // off2 = conv3d(out1, stride=1): M=1296, K=3456
    tot = (long long)NS * 3456;
    im2col_T<<<(unsigned)((tot + T - 1) / T), T>>>(out1, cols, 128, 8, 28, 28, 1, 0);
    gemm_h<256><<<dim3(11, NS / 256), 256, SMEMH256>>>(wh + WH_OFF2, cols, off2_b, off2, 1296, 3456);

    // out2 = deform_conv3d(out1, off2, stride=1): M=128, K=3456
    deform_T<<<dim3(NS / 32, 16), 864>>>(out1, off2, cols, 128, 16, 8, 28, 28, 1, 0);
    gemm_h<128><<<dim3(1, NS / 128), 256, SMEMH128>>>(wh + WH_CV2, cols, nullptr, out2, 128, 3456);

    bn_stats<<<128, 256>>>(out2, mean, istd);
    final_kernel<<<(128 * NS + T - 1) / T, T>>>(out2, bn2_g, bn2_b, mean, istd, res, out);
}

// round 9
// speedup vs baseline: 1.5968x; 1.1509x over previous
#include <cuda_runtime.h>
#include <cuda_fp16.h>
#include <math.h>
#include <stdint.h>

#define NBATCH 2
#define OD 8
#define OH 28
#define OW 28
#define S_OUT 6272
#define NS 12544

__device__ __half g_cols[43352064];  // [ns][K], max K=3456
__device__ __half g_wh[6262272];     // all four weight sets, half
__device__ float g_off1[8128512];    // [648][NS]
__device__ float g_off2[16257024];   // [1296][NS]
__device__ float g_out1[1605632];    // [128][NS]  (raw, pre-BN)
__device__ float g_out2[1605632];
__device__ float g_res[802816];      // [64][NS]
__device__ float g_mean[128];
__device__ float g_istd[128];

#define WH_OFF1 0
#define WH_CV1  1119744
#define WH_OFF2 1340928
#define WH_CV2  5819904

__device__ __forceinline__ uint32_t h2_as_u32(__half2 h) {
    return *(uint32_t*)&h;
}

// ---------------- fp32 -> fp16 ----------------
__global__ void f2h_kernel(const float* __restrict__ in, __half* __restrict__ out, int n) {
    int i = blockIdx.x * blockDim.x + threadIdx.x;
    if (i < n) out[i] = __float2half(in[i]);
}

// ---------------- maxpool ----------------
__global__ void maxpool_kernel(const float* __restrict__ x, float* __restrict__ res) {
    int i = blockIdx.x * blockDim.x + threadIdx.x;
    if (i >= 64 * NS) return;
    int ns = i % NS, c = i / NS;
    int n = ns / S_OUT, s = ns % S_OUT;
    int od = s / (OH * OW), oh = (s / OW) % OH, ow = s % OW;
    const float* xp = x + ((size_t)(n * 64 + c)) * 16 * 56 * 56;
    int d0 = od * 2 - 1, h0 = oh * 2 - 1, w0 = ow * 2 - 1;
    int dlo = d0 < 0 ? 0 : d0, dhi = d0 + 2 > 15 ? 15 : d0 + 2;
    int hlo = h0 < 0 ? 0 : h0, hhi = h0 + 2 > 55 ? 55 : h0 + 2;
    int wlo = w0 < 0 ? 0 : w0, whi = w0 + 2 > 55 ? 55 : w0 + 2;
    float m = -INFINITY;
    for (int dd = dlo; dd <= dhi; dd++)
        for (int hh = hlo; hh <= hhi; hh++)
            for (int ww = wlo; ww <= whi; ww++)
                m = fmaxf(m, xp[(dd * 56 + hh) * 56 + ww]);
    res[(size_t)c * NS + ns] = m;
}

// ---------------------------------------------------------------------------
// Block-staged im2col -> cols[ns][K] (half), optional fused BN+relu on input.
// Block: 864 threads = 27 warps (warp = tap, lane = ns). Grid (NS/32, C/8).
// ---------------------------------------------------------------------------
template <int C, int STRIDE, int NCDHW, int HASBN>
__global__ __launch_bounds__(864) void im2col_blk(
    const float* __restrict__ in, __half* __restrict__ cols,
    const float* __restrict__ gam, const float* __restrict__ bet,
    const float* __restrict__ mean, const float* __restrict__ istd,
    int Din, int Hin, int Win) {
    __shared__ float sbuf[216 * 33];
    const int K = C * 27;
    int tid = threadIdx.x;
    int nsl = tid & 31, tap = tid >> 5;
    int nsb = blockIdx.x * 32, g = blockIdx.y;
    int ns = nsb + nsl;
    int n = ns / S_OUT, s = ns % S_OUT;
    int od = s / (OH * OW), oh = (s / OW) % OH, ow = s % OW;
    int kd = tap / 9, kh = (tap / 3) % 3, kw = tap % 3;
    int id = od * STRIDE - 1 + kd, ih = oh * STRIDE - 1 + kh, iw = ow * STRIDE - 1 + kw;
    bool valid = id >= 0 && id < Din && ih >= 0 && ih < Hin && iw >= 0 && iw < Win;
    int Sin = Din * Hin * Win;
    int sidx = valid ? (id * Hin + ih) * Win + iw : 0;

#pragma unroll
    for (int cc = 0; cc < 8; cc++) {
        int c = g * 8 + cc;
        size_t base = NCDHW ? ((size_t)(n * C + c)) * Sin : ((size_t)c * NBATCH + n) * Sin;
        float v = valid ? in[base + sidx] : 0.f;
        if (HASBN) {
            float sc = gam[c] * istd[c];
            float sh = bet[c] - mean[c] * sc;
            v = valid ? fmaxf(sc * v + sh, 0.f) : 0.f;
        }
        sbuf[(cc * 27 + tap) * 33 + nsl] = v;
    }
    __syncthreads();
    // write 32 ns x 216 k, packed 4 halves (8B) per store
#pragma unroll
    for (int it = 0; it < 2; it++) {
        int j = it * 864 + tid;          // 0..1727 = 32*54
        int nsi = j / 54, kq = j % 54;
        __half2 h0 = __floats2half2_rn(sbuf[(kq * 4 + 0) * 33 + nsi],
                                       sbuf[(kq * 4 + 1) * 33 + nsi]);
        __half2 h1 = __floats2half2_rn(sbuf[(kq * 4 + 2) * 33 + nsi],
                                       sbuf[(kq * 4 + 3) * 33 + nsi]);
        *(uint2*)&cols[(size_t)(nsb + nsi) * K + g * 216 + kq * 4] =
            make_uint2(h2_as_u32(h0), h2_as_u32(h1));
    }
}

// ---------------------------------------------------------------------------
// Deformable im2col -> cols[ns][K] (half), optional fused BN+relu (per corner,
// required since relu precedes interpolation). Block 864, grid (NS/32, G).
// ---------------------------------------------------------------------------
template <int HASBN>
__global__ __launch_bounds__(864) void deform_T(
    const float* __restrict__ in, const float* __restrict__ off,
    __half* __restrict__ cols, int C, int G, int Din, int Hin, int Win,
    int stride, int ncdhw,
    const float* __restrict__ gam, const float* __restrict__ bet,
    const float* __restrict__ mean, const float* __restrict__ istd) {
    __shared__ float sbuf[216 * 33];
    int K = C * 27;
    int tid = threadIdx.x;
    int nsl = tid & 31, tap = tid >> 5;
    int nsb = blockIdx.x * 32, g = blockIdx.y;
    int ns = nsb + nsl;
    int n = ns / S_OUT, s = ns % S_OUT;
    int od = s / (OH * OW), oh = (s / OW) % OH, ow = s % OW;
    int kd = tap / 9, kh = (tap / 3) % 3, kw = tap % 3;

    size_t ob = ((size_t)(g * 3) * 27 + tap) * NS + ns;
    float pd = off[ob]                   + (float)(od * stride - 1 + kd);
    float ph = off[ob + (size_t)27 * NS] + (float)(oh * stride - 1 + kh);
    float pw = off[ob + (size_t)54 * NS] + (float)(ow * stride - 1 + kw);
    float d0f = floorf(pd), h0f = floorf(ph), w0f = floorf(pw);
    int d0 = (int)d0f, h0 = (int)h0f, w0 = (int)w0f;
    float fd = pd - d0f, fh = ph - h0f, fw = pw - w0f;

    float wt8[8]; int idx8[8];
    int Sin = Din * Hin * Win;
#pragma unroll
    for (int cr = 0; cr < 8; cr++) {
        int cd = cr >> 2, ch = (cr >> 1) & 1, cw = cr & 1;
        int di = d0 + cd, hi = h0 + ch, wi = w0 + cw;
        bool valid = (di >= 0) && (di < Din) && (hi >= 0) && (hi < Hin) &&
                     (wi >= 0) && (wi < Win);
        float wt = (cd ? fd : 1.f - fd) * (ch ? fh : 1.f - fh) * (cw ? fw : 1.f - fw);
        wt8[cr] = valid ? wt : 0.f;
        int dic = di < 0 ? 0 : (di > Din - 1 ? Din - 1 : di);
        int hic = hi < 0 ? 0 : (hi > Hin - 1 ? Hin - 1 : hi);
        int wic = wi < 0 ? 0 : (wi > Win - 1 ? Win - 1 : wi);
        idx8[cr] = (dic * Hin + hic) * Win + wic;
    }
#pragma unroll
    for (int cc = 0; cc < 8; cc++) {
        int c = g * 8 + cc;
        size_t base = ncdhw ? ((size_t)(n * C + c)) * Sin : ((size_t)c * NBATCH + n) * Sin;
        const float* bp = in + base;
        float acc = 0.f;
        if (HASBN) {
            float sc = gam[c] * istd[c];
            float sh = bet[c] - mean[c] * sc;
#pragma unroll
            for (int cr = 0; cr < 8; cr++)
                acc += wt8[cr] * fmaxf(sc * bp[idx8[cr]] + sh, 0.f);
        } else {
#pragma unroll
            for (int cr = 0; cr < 8; cr++) acc += wt8[cr] * bp[idx8[cr]];
        }
        sbuf[(cc * 27 + tap) * 33 + nsl] = acc;
    }
    __syncthreads();
#pragma unroll
    for (int it = 0; it < 2; it++) {
        int j = it * 864 + tid;
        int nsi = j / 54, kq = j % 54;
        __half2 h0 = __floats2half2_rn(sbuf[(kq * 4 + 0) * 33 + nsi],
                                       sbuf[(kq * 4 + 1) * 33 + nsi]);
        __half2 h1 = __floats2half2_rn(sbuf[(kq * 4 + 2) * 33 + nsi],
                                       sbuf[(kq * 4 + 3) * 33 + nsi]);
        *(uint2*)&cols[(size_t)(nsb + nsi) * K + g * 216 + kq * 4] =
            make_uint2(h2_as_u32(h0), h2_as_u32(h1));
    }
}

// ---------------------------------------------------------------------------
// FP16 mma.sync GEMM: C[M][NS] = A[M][K]*B^T (+bias). BM=128, BN {128,256},
// BK=32, 3-stage cp.async, one sync per k-tile, 8 warps 2x4.
// ---------------------------------------------------------------------------
#define HBK 32
#define HPH 40

__device__ __forceinline__ void cpasync16h(__half* dst, const __half* src, bool pred) {
    uint32_t d = (uint32_t)__cvta_generic_to_shared(dst);
    int sz = pred ? 16 : 0;
    asm volatile("cp.async.cg.shared.global [%0], [%1], 16, %2;\n"
                 :: "r"(d), "l"(src), "r"(sz));
}
__device__ __forceinline__ void mma_f16(float* c, uint32_t a0, uint32_t a1,
                                        uint32_t a2, uint32_t a3,
                                        uint32_t b0, uint32_t b1) {
    asm volatile(
        "mma.sync.aligned.m16n8k16.row.col.f32.f16.f16.f32 "
        "{%0,%1,%2,%3}, {%4,%5,%6,%7}, {%8,%9}, {%0,%1,%2,%3};\n"
        : "+f"(c[0]), "+f"(c[1]), "+f"(c[2]), "+f"(c[3])
        : "r"(a0), "r"(a1), "r"(a2), "r"(a3), "r"(b0), "r"(b1));
}

template <int BN>
__global__ __launch_bounds__(256) void gemm_h(
    const __half* __restrict__ A, const __half* __restrict__ B,
    const float* __restrict__ bias, float* __restrict__ C, int M, int K) {
    constexpr int BM = 128;
    constexpr int WN = BN / 4;
    constexpr int NT = WN / 8;
    constexpr int AH = BM * HPH;
    constexpr int BH = BN * HPH;
    constexpr int ASL = BM * HBK / 8 / 256;
    constexpr int BSL = BN * HBK / 8 / 256;

    extern __shared__ __half smh[];
    __half* Asm = smh;
    __half* Bsm = smh + 3 * AH;

    int tid = threadIdx.x;
    int warp = tid >> 5, lane = tid & 31;
    int wm = warp >> 2, wn = warp & 3;
    int rg = lane >> 2, cg = lane & 3;
    int row0 = blockIdx.x * BM;
    int col0 = blockIdx.y * BN;
    int T = K / HBK;

    int am[ASL], akq[ASL]; bool aok[ASL];
    const __half* asrc[ASL];
#pragma unroll
    for (int u = 0; u < ASL; u++) {
        int slot = u * 256 + tid;
        am[u] = slot >> 2; akq[u] = slot & 3;
        int gm = row0 + am[u];
        aok[u] = gm < M;
        asrc[u] = A + (size_t)(aok[u] ? gm : 0) * K + akq[u] * 8;
    }
    int bn_[BSL], bkq[BSL];
    const __half* bsrc[BSL];
#pragma unroll
    for (int u = 0; u < BSL; u++) {
        int slot = u * 256 + tid;
        bn_[u] = slot >> 2; bkq[u] = slot & 3;
        bsrc[u] = B + (size_t)(col0 + bn_[u]) * K + bkq[u] * 8;
    }

    float acc[4][NT][4];
#pragma unroll
    for (int i = 0; i < 4; i++)
#pragma unroll
        for (int j = 0; j < NT; j++)
#pragma unroll
            for (int r = 0; r < 4; r++) acc[i][j][r] = 0.f;

#pragma unroll
    for (int t = 0; t < 2; t++) {
#pragma unroll
        for (int u = 0; u < ASL; u++)
            cpasync16h(&Asm[t * AH + am[u] * HPH + akq[u] * 8], asrc[u] + t * HBK, aok[u]);
#pragma unroll
        for (int u = 0; u < BSL; u++)
            cpasync16h(&Bsm[t * BH + bn_[u] * HPH + bkq[u] * 8], bsrc[u] + t * HBK, true);
        asm volatile("cp.async.commit_group;\n");
    }

    for (int t = 0; t < T; t++) {
        asm volatile("cp.async.wait_group 1;\n");
        __syncthreads();
        int st = t % 3;
        const uint32_t* As32 = (const uint32_t*)(Asm + st * AH);
        const uint32_t* Bs32 = (const uint32_t*)(Bsm + st * BH);
#pragma unroll
        for (int ks = 0; ks < 2; ks++) {
            int kw = ks * 8 + cg;
            uint32_t af[4][4];
#pragma unroll
            for (int i = 0; i < 4; i++) {
                int mb = wm * 64 + i * 16;
                af[i][0] = As32[(mb + rg) * 20 + kw];
                af[i][1] = As32[(mb + 8 + rg) * 20 + kw];
                af[i][2] = As32[(mb + rg) * 20 + kw + 4];
                af[i][3] = As32[(mb + 8 + rg) * 20 + kw + 4];
            }
            uint32_t bf[NT][2];
#pragma unroll
            for (int j = 0; j < NT; j++) {
                int nb = wn * WN + j * 8 + rg;
                bf[j][0] = Bs32[nb * 20 + kw];
                bf[j][1] = Bs32[nb * 20 + kw + 4];
            }
#pragma unroll
            for (int i = 0; i < 4; i++)
#pragma unroll
                for (int j = 0; j < NT; j++)
                    mma_f16(acc[i][j], af[i][0], af[i][1], af[i][2], af[i][3],
                            bf[j][0], bf[j][1]);
        }
        int tn = t + 2;
        if (tn < T) {
            int sn = tn % 3;
            int k0 = tn * HBK;
#pragma unroll
            for (int u = 0; u < ASL; u++)
                cpasync16h(&Asm[sn * AH + am[u] * HPH + akq[u] * 8], asrc[u] + k0, aok[u]);
#pragma unroll
            for (int u = 0; u < BSL; u++)
                cpasync16h(&Bsm[sn * BH + bn_[u] * HPH + bkq[u] * 8], bsrc[u] + k0, true);
        }
        asm volatile("cp.async.commit_group;\n");
    }

#pragma unroll
    for (int i = 0; i < 4; i++) {
        int gm0 = row0 + wm * 64 + i * 16 + rg;
        int gm1 = gm0 + 8;
        float bv0 = (bias && gm0 < M) ? bias[gm0] : 0.f;
        float bv1 = (bias && gm1 < M) ? bias[gm1] : 0.f;
#pragma unroll
        for (int j = 0; j < NT; j++) {
            int gc = col0 + wn * WN + j * 8 + 2 * cg;
            if (gm0 < M)
                *(float2*)&C[(size_t)gm0 * NS + gc] =
                    make_float2(acc[i][j][0] + bv0, acc[i][j][1] + bv0);
            if (gm1 < M)
                *(float2*)&C[(size_t)gm1 * NS + gc] =
                    make_float2(acc[i][j][2] + bv1, acc[i][j][3] + bv1);
        }
    }
}

#define SMEMH256 (3 * (128 * HPH + 256 * HPH) * 2)
#define SMEMH128 (3 * (128 * HPH + 128 * HPH) * 2)

// ---------------- BN stats / final ----------------
__global__ void bn_stats(const float* __restrict__ x, float* __restrict__ mean,
                         float* __restrict__ istd) {
    int c = blockIdx.x;
    const float* row = x + (size_t)c * NS;
    float s = 0.f, s2 = 0.f;
    for (int i = threadIdx.x; i < NS / 4; i += blockDim.x) {
        float4 v = ((const float4*)row)[i];
        s += v.x + v.y + v.z + v.w;
        s2 += v.x * v.x + v.y * v.y + v.z * v.z + v.w * v.w;
    }
    __shared__ float sh[256], sh2[256];
    sh[threadIdx.x] = s; sh2[threadIdx.x] = s2;
    __syncthreads();
    for (int st = 128; st > 0; st >>= 1) {
        if (threadIdx.x < st) {
            sh[threadIdx.x] += sh[threadIdx.x + st];
            sh2[threadIdx.x] += sh2[threadIdx.x + st];
        }
        __syncthreads();
    }
    if (threadIdx.x == 0) {
        float m = sh[0] / (float)NS;
        float var = sh2[0] / (float)NS - m * m;
        mean[c] = m;
        istd[c] = rsqrtf(var + 1e-5f);
    }
}

__global__ void final_kernel(const float* __restrict__ raw, const float* __restrict__ gam,
                             const float* __restrict__ bet, const float* __restrict__ mean,
                             const float* __restrict__ istd, const float* __restrict__ res,
                             float* __restrict__ out) {
    int i = blockIdx.x * blockDim.x + threadIdx.x;
    if (i >= 128 * NS) return;
    int n = i / (128 * S_OUT);
    int co = (i / S_OUT) % 128;
    int s = i % S_OUT;
    float v = (raw[(size_t)co * NS + n * S_OUT + s] - mean[co]) * istd[co] * gam[co] + bet[co];
    v += res[(size_t)(co & 63) * NS + n * S_OUT + s];
    out[i] = fmaxf(v, 0.f);
}

// ---------------- host ----------------
extern "C" void kernel_launch(void* const* d_in, const int* in_sizes, int n_in,
                              void* d_out, int out_size) {
    (void)in_sizes; (void)n_in; (void)out_size;
    const float* x       = (const float*)d_in[0];
    const float* off1_w  = (const float*)d_in[1];
    const float* off1_b  = (const float*)d_in[2];
    const float* conv1_w = (const float*)d_in[3];
    const float* bn1_g   = (const float*)d_in[4];
    const float* bn1_b   = (const float*)d_in[5];
    const float* off2_w  = (const float*)d_in[6];
    const float* off2_b  = (const float*)d_in[7];
    const float* conv2_w = (const float*)d_in[8];
    const float* bn2_g   = (const float*)d_in[9];
    const float* bn2_b   = (const float*)d_in[10];
    float* out = (float*)d_out;

    __half *cols, *wh;
    float *off1, *off2, *out1, *out2, *res, *mean, *istd;
    cudaGetSymbolAddress((void**)&cols, g_cols);
    cudaGetSymbolAddress((void**)&wh,   g_wh);
    cudaGetSymbolAddress((void**)&off1, g_off1);
    cudaGetSymbolAddress((void**)&off2, g_off2);
    cudaGetSymbolAddress((void**)&out1, g_out1);
    cudaGetSymbolAddress((void**)&out2, g_out2);
    cudaGetSymbolAddress((void**)&res,  g_res);
    cudaGetSymbolAddress((void**)&mean, g_mean);
    cudaGetSymbolAddress((void**)&istd, g_istd);

    static int attr_done = 0;
    if (!attr_done) {
        cudaFuncSetAttribute(gemm_h<256>, cudaFuncAttributeMaxDynamicSharedMemorySize, SMEMH256);
        cudaFuncSetAttribute(gemm_h<128>, cudaFuncAttributeMaxDynamicSharedMemorySize, SMEMH128);
        attr_done = 1;
    }

    const int T = 256;

    f2h_kernel<<<(1119744 + T - 1) / T, T>>>(off1_w,  wh + WH_OFF1, 1119744);
    f2h_kernel<<<(221184  + T - 1) / T, T>>>(conv1_w, wh + WH_CV1,  221184);
    f2h_kernel<<<(4478976 + T - 1) / T, T>>>(off2_w,  wh + WH_OFF2, 4478976);
    f2h_kernel<<<(442368  + T - 1) / T, T>>>(conv2_w, wh + WH_CV2,  442368);

    maxpool_kernel<<<(64 * NS + T - 1) / T, T>>>(x, res);

    // off1 = conv3d(x, stride=2): M=648, K=1728
    im2col_blk<64, 2, 1, 0><<<dim3(NS / 32, 8), 864>>>(
        x, cols, nullptr, nullptr, nullptr, nullptr, 16, 56, 56);
    gemm_h<256><<<dim3(6, NS / 256), 256, SMEMH256>>>(wh + WH_OFF1, cols, off1_b, off1, 648, 1728);

    // out1 = deform_conv3d(x, off1, stride=2): M=128, K=1728
    deform_T<0><<<dim3(NS / 32, 8), 864>>>(
        x, off1, cols, 64, 8, 16, 56, 56, 2, 1, nullptr, nullptr, nullptr, nullptr);
    gemm_h<128><<<dim3(1, NS / 128), 256, SMEMH128>>>(wh + WH_CV1, cols, nullptr, out1, 128, 1728);

    bn_stats<<<128, 256>>>(out1, mean, istd);

    // off2 = conv3d(relu(bn1(out1)), stride=1): M=1296, K=3456  (BN fused in im2col)
    im2col_blk<128, 1, 0, 1><<<dim3(NS / 32, 16), 864>>>(
        out1, cols, bn1_g, bn1_b, mean, istd, 8, 28, 28);
    gemm_h<256><<<dim3(11, NS / 256), 256, SMEMH256>>>(wh + WH_OFF2, cols, off2_b, off2, 1296, 3456);

    // out2 = deform_conv3d(relu(bn1(out1)), off2, stride=1): M=128, K=3456
    deform_T<1><<<dim3(NS / 32, 16), 864>>>(
        out1, off2, cols, 128, 16, 8, 28, 28, 1, 0, bn1_g, bn1_b, mean, istd);
    gemm_h<128><<<dim3(1, NS / 128), 256, SMEMH128>>>(wh + WH_CV2, cols, nullptr, out2, 128, 3456);

    bn_stats<<<128, 256>>>(out2, mean, istd);
    final_kernel<<<(128 * NS + T - 1) / T, T>>>(out2, bn2_g, bn2_b, mean, istd, res, out);
}

// round 10
// speedup vs baseline: 1.6716x; 1.0469x over previous
#include <cuda_runtime.h>
#include <cuda_fp16.h>
#include <math.h>
#include <stdint.h>

#define NBATCH 2
#define OD 8
#define OH 28
#define OW 28
#define S_OUT 6272
#define NS 12544

__device__ __half g_cols[43352064];  // [ns][K], max K=3456
__device__ __half g_wh[6262272];     // all four weight sets, half
__device__ __half g_xh[6422528];     // x as half (NCDHW)
__device__ __half g_act[1605632];    // relu(bn1(out1)) as half, [c][NS]
__device__ float g_off1[8128512];    // [648][NS]
__device__ float g_off2[16257024];   // [1296][NS]
__device__ float g_out1[1605632];    // [128][NS]  (raw, pre-BN)
__device__ float g_out2[1605632];
__device__ float g_res[802816];      // [64][NS]
__device__ float g_mean[128];
__device__ float g_istd[128];

#define WH_OFF1 0
#define WH_CV1  1119744
#define WH_OFF2 1340928
#define WH_CV2  5819904

__device__ __forceinline__ uint32_t h2_as_u32(__half2 h) {
    return *(uint32_t*)&h;
}

// ---------------- fp32 -> fp16 (scalar, for weights) ----------------
__global__ void f2h_kernel(const float* __restrict__ in, __half* __restrict__ out, int n) {
    int i = blockIdx.x * blockDim.x + threadIdx.x;
    if (i < n) out[i] = __float2half(in[i]);
}

// ---------------- fp32 -> fp16, vectorized x4 ----------------
__global__ void f2h4_kernel(const float* __restrict__ in, __half* __restrict__ out, int n4) {
    int i = blockIdx.x * blockDim.x + threadIdx.x;
    if (i >= n4) return;
    float4 v = ((const float4*)in)[i];
    __half2 h0 = __floats2half2_rn(v.x, v.y);
    __half2 h1 = __floats2half2_rn(v.z, v.w);
    ((uint2*)out)[i] = make_uint2(h2_as_u32(h0), h2_as_u32(h1));
}

// ---------------- BN+relu -> fp16 act, vectorized x4 ----------------
__global__ void bn_act_h(const float* __restrict__ in, __half* __restrict__ out,
                         const float* __restrict__ gam, const float* __restrict__ bet,
                         const float* __restrict__ mean, const float* __restrict__ istd) {
    int i = blockIdx.x * blockDim.x + threadIdx.x;   // over 128*NS/4
    if (i >= 128 * NS / 4) return;
    int c = (i * 4) / NS;
    float sc = gam[c] * istd[c];
    float sh = bet[c] - mean[c] * sc;
    float4 v = ((const float4*)in)[i];
    v.x = fmaxf(sc * v.x + sh, 0.f);
    v.y = fmaxf(sc * v.y + sh, 0.f);
    v.z = fmaxf(sc * v.z + sh, 0.f);
    v.w = fmaxf(sc * v.w + sh, 0.f);
    __half2 h0 = __floats2half2_rn(v.x, v.y);
    __half2 h1 = __floats2half2_rn(v.z, v.w);
    ((uint2*)out)[i] = make_uint2(h2_as_u32(h0), h2_as_u32(h1));
}

// ---------------- maxpool (fp32 x -> fp32 residual, exact path) ----------------
__global__ void maxpool_kernel(const float* __restrict__ x, float* __restrict__ res) {
    int i = blockIdx.x * blockDim.x + threadIdx.x;
    if (i >= 64 * NS) return;
    int ns = i % NS, c = i / NS;
    int n = ns / S_OUT, s = ns % S_OUT;
    int od = s / (OH * OW), oh = (s / OW) % OH, ow = s % OW;
    const float* xp = x + ((size_t)(n * 64 + c)) * 16 * 56 * 56;
    int d0 = od * 2 - 1, h0 = oh * 2 - 1, w0 = ow * 2 - 1;
    int dlo = d0 < 0 ? 0 : d0, dhi = d0 + 2 > 15 ? 15 : d0 + 2;
    int hlo = h0 < 0 ? 0 : h0, hhi = h0 + 2 > 55 ? 55 : h0 + 2;
    int wlo = w0 < 0 ? 0 : w0, whi = w0 + 2 > 55 ? 55 : w0 + 2;
    float m = -INFINITY;
    for (int dd = dlo; dd <= dhi; dd++)
        for (int hh = hlo; hh <= hhi; hh++)
            for (int ww = wlo; ww <= whi; ww++)
                m = fmaxf(m, xp[(dd * 56 + hh) * 56 + ww]);
    res[(size_t)c * NS + ns] = m;
}

// ---------------------------------------------------------------------------
// Block-staged im2col (fp16 input) -> cols[ns][K] (half).
// Block: 864 threads = 27 warps (warp = tap, lane = ns). Grid (NS/32, C/8).
// ---------------------------------------------------------------------------
template <int C, int STRIDE, int NCDHW>
__global__ __launch_bounds__(864) void im2col_blk(
    const __half* __restrict__ in, __half* __restrict__ cols,
    int Din, int Hin, int Win) {
    __shared__ float sbuf[216 * 33];
    const int K = C * 27;
    int tid = threadIdx.x;
    int nsl = tid & 31, tap = tid >> 5;
    int nsb = blockIdx.x * 32, g = blockIdx.y;
    int ns = nsb + nsl;
    int n = ns / S_OUT, s = ns % S_OUT;
    int od = s / (OH * OW), oh = (s / OW) % OH, ow = s % OW;
    int kd = tap / 9, kh = (tap / 3) % 3, kw = tap % 3;
    int id = od * STRIDE - 1 + kd, ih = oh * STRIDE - 1 + kh, iw = ow * STRIDE - 1 + kw;
    bool valid = id >= 0 && id < Din && ih >= 0 && ih < Hin && iw >= 0 && iw < Win;
    int Sin = Din * Hin * Win;
    int sidx = valid ? (id * Hin + ih) * Win + iw : 0;

#pragma unroll
    for (int cc = 0; cc < 8; cc++) {
        int c = g * 8 + cc;
        size_t base = NCDHW ? ((size_t)(n * C + c)) * Sin : ((size_t)c * NBATCH + n) * Sin;
        float v = valid ? __half2float(in[base + sidx]) : 0.f;
        sbuf[(cc * 27 + tap) * 33 + nsl] = v;
    }
    __syncthreads();
#pragma unroll
    for (int it = 0; it < 2; it++) {
        int j = it * 864 + tid;          // 0..1727 = 32*54
        int nsi = j / 54, kq = j % 54;
        __half2 h0 = __floats2half2_rn(sbuf[(kq * 4 + 0) * 33 + nsi],
                                       sbuf[(kq * 4 + 1) * 33 + nsi]);
        __half2 h1 = __floats2half2_rn(sbuf[(kq * 4 + 2) * 33 + nsi],
                                       sbuf[(kq * 4 + 3) * 33 + nsi]);
        *(uint2*)&cols[(size_t)(nsb + nsi) * K + g * 216 + kq * 4] =
            make_uint2(h2_as_u32(h0), h2_as_u32(h1));
    }
}

// ---------------------------------------------------------------------------
// Deformable im2col (fp16 input) -> cols[ns][K] (half), smem staged.
// Block 864, grid (NS/32, G). Interpolation in fp32.
// ---------------------------------------------------------------------------
__global__ __launch_bounds__(864) void deform_T(
    const __half* __restrict__ in, const float* __restrict__ off,
    __half* __restrict__ cols, int C, int G, int Din, int Hin, int Win,
    int stride, int ncdhw) {
    __shared__ float sbuf[216 * 33];
    int K = C * 27;
    int tid = threadIdx.x;
    int nsl = tid & 31, tap = tid >> 5;
    int nsb = blockIdx.x * 32, g = blockIdx.y;
    int ns = nsb + nsl;
    int n = ns / S_OUT, s = ns % S_OUT;
    int od = s / (OH * OW), oh = (s / OW) % OH, ow = s % OW;
    int kd = tap / 9, kh = (tap / 3) % 3, kw = tap % 3;

    size_t ob = ((size_t)(g * 3) * 27 + tap) * NS + ns;
    float pd = off[ob]                   + (float)(od * stride - 1 + kd);
    float ph = off[ob + (size_t)27 * NS] + (float)(oh * stride - 1 + kh);
    float pw = off[ob + (size_t)54 * NS] + (float)(ow * stride - 1 + kw);
    float d0f = floorf(pd), h0f = floorf(ph), w0f = floorf(pw);
    int d0 = (int)d0f, h0 = (int)h0f, w0 = (int)w0f;
    float fd = pd - d0f, fh = ph - h0f, fw = pw - w0f;

    float wt8[8]; int idx8[8];
    int Sin = Din * Hin * Win;
#pragma unroll
    for (int cr = 0; cr < 8; cr++) {
        int cd = cr >> 2, ch = (cr >> 1) & 1, cw = cr & 1;
        int di = d0 + cd, hi = h0 + ch, wi = w0 + cw;
        bool valid = (di >= 0) && (di < Din) && (hi >= 0) && (hi < Hin) &&
                     (wi >= 0) && (wi < Win);
        float wt = (cd ? fd : 1.f - fd) * (ch ? fh : 1.f - fh) * (cw ? fw : 1.f - fw);
        wt8[cr] = valid ? wt : 0.f;
        int dic = di < 0 ? 0 : (di > Din - 1 ? Din - 1 : di);
        int hic = hi < 0 ? 0 : (hi > Hin - 1 ? Hin - 1 : hi);
        int wic = wi < 0 ? 0 : (wi > Win - 1 ? Win - 1 : wi);
        idx8[cr] = (dic * Hin + hic) * Win + wic;
    }
#pragma unroll
    for (int cc = 0; cc < 8; cc++) {
        int c = g * 8 + cc;
        size_t base = ncdhw ? ((size_t)(n * C + c)) * Sin : ((size_t)c * NBATCH + n) * Sin;
        const __half* bp = in + base;
        float acc = 0.f;
#pragma unroll
        for (int cr = 0; cr < 8; cr++) acc += wt8[cr] * __half2float(bp[idx8[cr]]);
        sbuf[(cc * 27 + tap) * 33 + nsl] = acc;
    }
    __syncthreads();
#pragma unroll
    for (int it = 0; it < 2; it++) {
        int j = it * 864 + tid;
        int nsi = j / 54, kq = j % 54;
        __half2 h0 = __floats2half2_rn(sbuf[(kq * 4 + 0) * 33 + nsi],
                                       sbuf[(kq * 4 + 1) * 33 + nsi]);
        __half2 h1 = __floats2half2_rn(sbuf[(kq * 4 + 2) * 33 + nsi],
                                       sbuf[(kq * 4 + 3) * 33 + nsi]);
        *(uint2*)&cols[(size_t)(nsb + nsi) * K + g * 216 + kq * 4] =
            make_uint2(h2_as_u32(h0), h2_as_u32(h1));
    }
}

// ---------------------------------------------------------------------------
// FP16 mma.sync GEMM (unchanged): C[M][NS] = A[M][K]*B^T (+bias).
// ---------------------------------------------------------------------------
#define HBK 32
#define HPH 40

__device__ __forceinline__ void cpasync16h(__half* dst, const __half* src, bool pred) {
    uint32_t d = (uint32_t)__cvta_generic_to_shared(dst);
    int sz = pred ? 16 : 0;
    asm volatile("cp.async.cg.shared.global [%0], [%1], 16, %2;\n"
                 :: "r"(d), "l"(src), "r"(sz));
}
__device__ __forceinline__ void mma_f16(float* c, uint32_t a0, uint32_t a1,
                                        uint32_t a2, uint32_t a3,
                                        uint32_t b0, uint32_t b1) {
    asm volatile(
        "mma.sync.aligned.m16n8k16.row.col.f32.f16.f16.f32 "
        "{%0,%1,%2,%3}, {%4,%5,%6,%7}, {%8,%9}, {%0,%1,%2,%3};\n"
        : "+f"(c[0]), "+f"(c[1]), "+f"(c[2]), "+f"(c[3])
        : "r"(a0), "r"(a1), "r"(a2), "r"(a3), "r"(b0), "r"(b1));
}

template <int BN>
__global__ __launch_bounds__(256) void gemm_h(
    const __half* __restrict__ A, const __half* __restrict__ B,
    const float* __restrict__ bias, float* __restrict__ C, int M, int K) {
    constexpr int BM = 128;
    constexpr int WN = BN / 4;
    constexpr int NT = WN / 8;
    constexpr int AH = BM * HPH;
    constexpr int BH = BN * HPH;
    constexpr int ASL = BM * HBK / 8 / 256;
    constexpr int BSL = BN * HBK / 8 / 256;

    extern __shared__ __half smh[];
    __half* Asm = smh;
    __half* Bsm = smh + 3 * AH;

    int tid = threadIdx.x;
    int warp = tid >> 5, lane = tid & 31;
    int wm = warp >> 2, wn = warp & 3;
    int rg = lane >> 2, cg = lane & 3;
    int row0 = blockIdx.x * BM;
    int col0 = blockIdx.y * BN;
    int T = K / HBK;

    int am[ASL], akq[ASL]; bool aok[ASL];
    const __half* asrc[ASL];
#pragma unroll
    for (int u = 0; u < ASL; u++) {
        int slot = u * 256 + tid;
        am[u] = slot >> 2; akq[u] = slot & 3;
        int gm = row0 + am[u];
        aok[u] = gm < M;
        asrc[u] = A + (size_t)(aok[u] ? gm : 0) * K + akq[u] * 8;
    }
    int bn_[BSL], bkq[BSL];
    const __half* bsrc[BSL];
#pragma unroll
    for (int u = 0; u < BSL; u++) {
        int slot = u * 256 + tid;
        bn_[u] = slot >> 2; bkq[u] = slot & 3;
        bsrc[u] = B + (size_t)(col0 + bn_[u]) * K + bkq[u] * 8;
    }

    float acc[4][NT][4];
#pragma unroll
    for (int i = 0; i < 4; i++)
#pragma unroll
        for (int j = 0; j < NT; j++)
#pragma unroll
            for (int r = 0; r < 4; r++) acc[i][j][r] = 0.f;

#pragma unroll
    for (int t = 0; t < 2; t++) {
#pragma unroll
        for (int u = 0; u < ASL; u++)
            cpasync16h(&Asm[t * AH + am[u] * HPH + akq[u] * 8], asrc[u] + t * HBK, aok[u]);
#pragma unroll
        for (int u = 0; u < BSL; u++)
            cpasync16h(&Bsm[t * BH + bn_[u] * HPH + bkq[u] * 8], bsrc[u] + t * HBK, true);
        asm volatile("cp.async.commit_group;\n");
    }

    for (int t = 0; t < T; t++) {
        asm volatile("cp.async.wait_group 1;\n");
        __syncthreads();
        int st = t % 3;
        const uint32_t* As32 = (const uint32_t*)(Asm + st * AH);
        const uint32_t* Bs32 = (const uint32_t*)(Bsm + st * BH);
#pragma unroll
        for (int ks = 0; ks < 2; ks++) {
            int kw = ks * 8 + cg;
            uint32_t af[4][4];
#pragma unroll
            for (int i = 0; i < 4; i++) {
                int mb = wm * 64 + i * 16;
                af[i][0] = As32[(mb + rg) * 20 + kw];
                af[i][1] = As32[(mb + 8 + rg) * 20 + kw];
                af[i][2] = As32[(mb + rg) * 20 + kw + 4];
                af[i][3] = As32[(mb + 8 + rg) * 20 + kw + 4];
            }
            uint32_t bf[NT][2];
#pragma unroll
            for (int j = 0; j < NT; j++) {
                int nb = wn * WN + j * 8 + rg;
                bf[j][0] = Bs32[nb * 20 + kw];
                bf[j][1] = Bs32[nb * 20 + kw + 4];
            }
#pragma unroll
            for (int i = 0; i < 4; i++)
#pragma unroll
                for (int j = 0; j < NT; j++)
                    mma_f16(acc[i][j], af[i][0], af[i][1], af[i][2], af[i][3],
                            bf[j][0], bf[j][1]);
        }
        int tn = t + 2;
        if (tn < T) {
            int sn = tn % 3;
            int k0 = tn * HBK;
#pragma unroll
            for (int u = 0; u < ASL; u++)
                cpasync16h(&Asm[sn * AH + am[u] * HPH + akq[u] * 8], asrc[u] + k0, aok[u]);
#pragma unroll
            for (int u = 0; u < BSL; u++)
                cpasync16h(&Bsm[sn * BH + bn_[u] * HPH + bkq[u] * 8], bsrc[u] + k0, true);
        }
        asm volatile("cp.async.commit_group;\n");
    }

#pragma unroll
    for (int i = 0; i < 4; i++) {
        int gm0 = row0 + wm * 64 + i * 16 + rg;
        int gm1 = gm0 + 8;
        float bv0 = (bias && gm0 < M) ? bias[gm0] : 0.f;
        float bv1 = (bias && gm1 < M) ? bias[gm1] : 0.f;
#pragma unroll
        for (int j = 0; j < NT; j++) {
            int gc = col0 + wn * WN + j * 8 + 2 * cg;
            if (gm0 < M)
                *(float2*)&C[(size_t)gm0 * NS + gc] =
                    make_float2(acc[i][j][0] + bv0, acc[i][j][1] + bv0);
            if (gm1 < M)
                *(float2*)&C[(size_t)gm1 * NS + gc] =
                    make_float2(acc[i][j][2] + bv1, acc[i][j][3] + bv1);
        }
    }
}

#define SMEMH256 (3 * (128 * HPH + 256 * HPH) * 2)
#define SMEMH128 (3 * (128 * HPH + 128 * HPH) * 2)

// ---------------- BN stats / final ----------------
__global__ void bn_stats(const float* __restrict__ x, float* __restrict__ mean,
                         float* __restrict__ istd) {
    int c = blockIdx.x;
    const float* row = x + (size_t)c * NS;
    float s = 0.f, s2 = 0.f;
    for (int i = threadIdx.x; i < NS / 4; i += blockDim.x) {
        float4 v = ((const float4*)row)[i];
        s += v.x + v.y + v.z + v.w;
        s2 += v.x * v.x + v.y * v.y + v.z * v.z + v.w * v.w;
    }
    __shared__ float sh[256], sh2[256];
    sh[threadIdx.x] = s; sh2[threadIdx.x] = s2;
    __syncthreads();
    for (int st = 128; st > 0; st >>= 1) {
        if (threadIdx.x < st) {
            sh[threadIdx.x] += sh[threadIdx.x + st];
            sh2[threadIdx.x] += sh2[threadIdx.x + st];
        }
        __syncthreads();
    }
    if (threadIdx.x == 0) {
        float m = sh[0] / (float)NS;
        float var = sh2[0] / (float)NS - m * m;
        mean[c] = m;
        istd[c] = rsqrtf(var + 1e-5f);
    }
}

__global__ void final_kernel(const float* __restrict__ raw, const float* __restrict__ gam,
                             const float* __restrict__ bet, const float* __restrict__ mean,
                             const float* __restrict__ istd, const float* __restrict__ res,
                             float* __restrict__ out) {
    int i = blockIdx.x * blockDim.x + threadIdx.x;
    if (i >= 128 * NS) return;
    int n = i / (128 * S_OUT);
    int co = (i / S_OUT) % 128;
    int s = i % S_OUT;
    float v = (raw[(size_t)co * NS + n * S_OUT + s] - mean[co]) * istd[co] * gam[co] + bet[co];
    v += res[(size_t)(co & 63) * NS + n * S_OUT + s];
    out[i] = fmaxf(v, 0.f);
}

// ---------------- host ----------------
extern "C" void kernel_launch(void* const* d_in, const int* in_sizes, int n_in,
                              void* d_out, int out_size) {
    (void)in_sizes; (void)n_in; (void)out_size;
    const float* x       = (const float*)d_in[0];
    const float* off1_w  = (const float*)d_in[1];
    const float* off1_b  = (const float*)d_in[2];
    const float* conv1_w = (const float*)d_in[3];
    const float* bn1_g   = (const float*)d_in[4];
    const float* bn1_b   = (const float*)d_in[5];
    const float* off2_w  = (const float*)d_in[6];
    const float* off2_b  = (const float*)d_in[7];
    const float* conv2_w = (const float*)d_in[8];
    const float* bn2_g   = (const float*)d_in[9];
    const float* bn2_b   = (const float*)d_in[10];
    float* out = (float*)d_out;

    __half *cols, *wh, *xh, *act;
    float *off1, *off2, *out1, *out2, *res, *mean, *istd;
    cudaGetSymbolAddress((void**)&cols, g_cols);
    cudaGetSymbolAddress((void**)&wh,   g_wh);
    cudaGetSymbolAddress((void**)&xh,   g_xh);
    cudaGetSymbolAddress((void**)&act,  g_act);
    cudaGetSymbolAddress((void**)&off1, g_off1);
    cudaGetSymbolAddress((void**)&off2, g_off2);
    cudaGetSymbolAddress((void**)&out1, g_out1);
    cudaGetSymbolAddress((void**)&out2, g_out2);
    cudaGetSymbolAddress((void**)&res,  g_res);
    cudaGetSymbolAddress((void**)&mean, g_mean);
    cudaGetSymbolAddress((void**)&istd, g_istd);

    static int attr_done = 0;
    if (!attr_done) {
        cudaFuncSetAttribute(gemm_h<256>, cudaFuncAttributeMaxDynamicSharedMemorySize, SMEMH256);
        cudaFuncSetAttribute(gemm_h<128>, cudaFuncAttributeMaxDynamicSharedMemorySize, SMEMH128);
        attr_done = 1;
    }

    const int T = 256;

    // convert weights + x to half
    f2h_kernel<<<(1119744 + T - 1) / T, T>>>(off1_w,  wh + WH_OFF1, 1119744);
    f2h_kernel<<<(221184  + T - 1) / T, T>>>(conv1_w, wh + WH_CV1,  221184);
    f2h_kernel<<<(4478976 + T - 1) / T, T>>>(off2_w,  wh + WH_OFF2, 4478976);
    f2h_kernel<<<(442368  + T - 1) / T, T>>>(conv2_w, wh + WH_CV2,  442368);
    f2h4_kernel<<<(6422528 / 4 + T - 1) / T, T>>>(x, xh, 6422528 / 4);

    maxpool_kernel<<<(64 * NS + T - 1) / T, T>>>(x, res);

    // off1 = conv3d(x, stride=2): M=648, K=1728
    im2col_blk<64, 2, 1><<<dim3(NS / 32, 8), 864>>>(xh, cols, 16, 56, 56);
    gemm_h<256><<<dim3(6, NS / 256), 256, SMEMH256>>>(wh + WH_OFF1, cols, off1_b, off1, 648, 1728);

    // out1 = deform_conv3d(x, off1, stride=2): M=128, K=1728
    deform_T<<<dim3(NS / 32, 8), 864>>>(xh, off1, cols, 64, 8, 16, 56, 56, 2, 1);
    gemm_h<128><<<dim3(1, NS / 128), 256, SMEMH128>>>(wh + WH_CV1, cols, nullptr, out1, 128, 1728);

    bn_stats<<<128, 256>>>(out1, mean, istd);
    bn_act_h<<<(128 * NS / 4 + T - 1) / T, T>>>(out1, act, bn1_g, bn1_b, mean, istd);

    // off2 = conv3d(act, stride=1): M=1296, K=3456
    im2col_blk<128, 1, 0><<<dim3(NS / 32, 16), 864>>>(act, cols, 8, 28, 28);
    gemm_h<256><<<dim3(11, NS / 256), 256, SMEMH256>>>(wh + WH_OFF2, cols, off2_b, off2, 1296, 3456);

    // out2 = deform_conv3d(act, off2, stride=1): M=128, K=3456
    deform_T<<<dim3(NS / 32, 16), 864>>>(act, off2, cols, 128, 16, 8, 28, 28, 1, 0);
    gemm_h<128><<<dim3(1, NS / 128), 256, SMEMH128>>>(wh + WH_CV2, cols, nullptr, out2, 128, 3456);

    bn_stats<<<128, 256>>>(out2, mean, istd);
    final_kernel<<<(128 * NS + T - 1) / T, T>>>(out2, bn2_g, bn2_b, mean, istd, res, out);
}

// round 12
// speedup vs baseline: 1.6963x; 1.0147x over previous
#include <cuda_runtime.h>
#include <cuda_fp16.h>
#include <math.h>
#include <stdint.h>

#define NBATCH 2
#define OD 8
#define OH 28
#define OW 28
#define S_OUT 6272
#define NS 12544

__device__ __half g_cols[43352064];  // [ns][K], max K=3456
__device__ __half g_wh[6262272];     // all four weight sets, half
__device__ __half g_xh[6422528];     // x as half (NCDHW)
__device__ __half g_act[1605632];    // relu(bn1(out1)) as half, [c][NS]
__device__ float g_off1[8128512];    // [648][NS]
__device__ float g_off2[16257024];   // [1296][NS]
__device__ float g_out1[1605632];    // [128][NS]  (raw, pre-BN)
__device__ float g_out2[1605632];
__device__ float g_res[802816];      // [64][NS]
__device__ float g_mean[128];
__device__ float g_istd[128];

#define WH_OFF1 0
#define WH_CV1  1119744
#define WH_OFF2 1340928
#define WH_CV2  5819904
#define N_OFF1W 1119744
#define N_CV1W  221184
#define N_OFF2W 4478976
#define N_CV2W  442368

__device__ __forceinline__ uint32_t h2_as_u32(__half2 h) {
    return *(uint32_t*)&h;
}

// ---------------- all four weight sets fp32 -> fp16, one launch ----------------
__global__ void f2h_all(const float* __restrict__ w0, const float* __restrict__ w1,
                        const float* __restrict__ w2, const float* __restrict__ w3,
                        __half* __restrict__ out) {
    const int n40 = N_OFF1W / 4, n41 = N_CV1W / 4, n42 = N_OFF2W / 4, n43 = N_CV2W / 4;
    int i = blockIdx.x * blockDim.x + threadIdx.x;
    const float* src;
    int li;
    __half* dst;
    if (i < n40)                { src = w0; li = i;               dst = out + WH_OFF1; }
    else if (i < n40+n41)       { src = w1; li = i - n40;         dst = out + WH_CV1; }
    else if (i < n40+n41+n42)   { src = w2; li = i - n40-n41;     dst = out + WH_OFF2; }
    else if (i < n40+n41+n42+n43){ src = w3; li = i - n40-n41-n42; dst = out + WH_CV2; }
    else return;
    float4 v = ((const float4*)src)[li];
    __half2 h0 = __floats2half2_rn(v.x, v.y);
    __half2 h1 = __floats2half2_rn(v.z, v.w);
    ((uint2*)dst)[li] = make_uint2(h2_as_u32(h0), h2_as_u32(h1));
}

// ---------------- fp32 -> fp16, vectorized x4 ----------------
__global__ void f2h4_kernel(const float* __restrict__ in, __half* __restrict__ out, int n4) {
    int i = blockIdx.x * blockDim.x + threadIdx.x;
    if (i >= n4) return;
    float4 v = ((const float4*)in)[i];
    __half2 h0 = __floats2half2_rn(v.x, v.y);
    __half2 h1 = __floats2half2_rn(v.z, v.w);
    ((uint2*)out)[i] = make_uint2(h2_as_u32(h0), h2_as_u32(h1));
}

// ---------------- BN+relu -> fp16 act, vectorized x4 ----------------
__global__ void bn_act_h(const float* __restrict__ in, __half* __restrict__ out,
                         const float* __restrict__ gam, const float* __restrict__ bet,
                         const float* __restrict__ mean, const float* __restrict__ istd) {
    int i = blockIdx.x * blockDim.x + threadIdx.x;
    if (i >= 128 * NS / 4) return;
    int c = (i * 4) / NS;
    float sc = gam[c] * istd[c];
    float sh = bet[c] - mean[c] * sc;
    float4 v = ((const float4*)in)[i];
    v.x = fmaxf(sc * v.x + sh, 0.f);
    v.y = fmaxf(sc * v.y + sh, 0.f);
    v.z = fmaxf(sc * v.z + sh, 0.f);
    v.w = fmaxf(sc * v.w + sh, 0.f);
    __half2 h0 = __floats2half2_rn(v.x, v.y);
    __half2 h1 = __floats2half2_rn(v.z, v.w);
    ((uint2*)out)[i] = make_uint2(h2_as_u32(h0), h2_as_u32(h1));
}

// ---------------- maxpool (fp32 x -> fp32 residual, exact path) ----------------
__global__ void maxpool_kernel(const float* __restrict__ x, float* __restrict__ res) {
    int i = blockIdx.x * blockDim.x + threadIdx.x;
    if (i >= 64 * NS) return;
    int ns = i % NS, c = i / NS;
    int n = ns / S_OUT, s = ns % S_OUT;
    int od = s / (OH * OW), oh = (s / OW) % OH, ow = s % OW;
    const float* xp = x + ((size_t)(n * 64 + c)) * 16 * 56 * 56;
    int d0 = od * 2 - 1, h0 = oh * 2 - 1, w0 = ow * 2 - 1;
    int dlo = d0 < 0 ? 0 : d0, dhi = d0 + 2 > 15 ? 15 : d0 + 2;
    int hlo = h0 < 0 ? 0 : h0, hhi = h0 + 2 > 55 ? 55 : h0 + 2;
    int wlo = w0 < 0 ? 0 : w0, whi = w0 + 2 > 55 ? 55 : w0 + 2;
    float m = -INFINITY;
    for (int dd = dlo; dd <= dhi; dd++)
        for (int hh = hlo; hh <= hhi; hh++)
            for (int ww = wlo; ww <= whi; ww++)
                m = fmaxf(m, xp[(dd * 56 + hh) * 56 + ww]);
    res[(size_t)c * NS + ns] = m;
}

// ---------------------------------------------------------------------------
// Block-staged im2col (fp16 input) -> cols[ns][K] (half).
// ---------------------------------------------------------------------------
template <int C, int STRIDE, int NCDHW>
__global__ __launch_bounds__(864) void im2col_blk(
    const __half* __restrict__ in, __half* __restrict__ cols,
    int Din, int Hin, int Win) {
    __shared__ float sbuf[216 * 33];
    const int K = C * 27;
    int tid = threadIdx.x;
    int nsl = tid & 31, tap = tid >> 5;
    int nsb = blockIdx.x * 32, g = blockIdx.y;
    int ns = nsb + nsl;
    int n = ns / S_OUT, s = ns % S_OUT;
    int od = s / (OH * OW), oh = (s / OW) % OH, ow = s % OW;
    int kd = tap / 9, kh = (tap / 3) % 3, kw = tap % 3;
    int id = od * STRIDE - 1 + kd, ih = oh * STRIDE - 1 + kh, iw = ow * STRIDE - 1 + kw;
    bool valid = id >= 0 && id < Din && ih >= 0 && ih < Hin && iw >= 0 && iw < Win;
    int Sin = Din * Hin * Win;
    int sidx = valid ? (id * Hin + ih) * Win + iw : 0;

#pragma unroll
    for (int cc = 0; cc < 8; cc++) {
        int c = g * 8 + cc;
        size_t base = NCDHW ? ((size_t)(n * C + c)) * Sin : ((size_t)c * NBATCH + n) * Sin;
        float v = valid ? __half2float(in[base + sidx]) : 0.f;
        sbuf[(cc * 27 + tap) * 33 + nsl] = v;
    }
    __syncthreads();
#pragma unroll
    for (int it = 0; it < 2; it++) {
        int j = it * 864 + tid;
        int nsi = j / 54, kq = j % 54;
        __half2 h0 = __floats2half2_rn(sbuf[(kq * 4 + 0) * 33 + nsi],
                                       sbuf[(kq * 4 + 1) * 33 + nsi]);
        __half2 h1 = __floats2half2_rn(sbuf[(kq * 4 + 2) * 33 + nsi],
                                       sbuf[(kq * 4 + 3) * 33 + nsi]);
        *(uint2*)&cols[(size_t)(nsb + nsi) * K + g * 216 + kq * 4] =
            make_uint2(h2_as_u32(h0), h2_as_u32(h1));
    }
}

// ---------------------------------------------------------------------------
// Deformable im2col (fp16 input) -> cols[ns][K] (half), smem staged.
// ---------------------------------------------------------------------------
__global__ __launch_bounds__(864) void deform_T(
    const __half* __restrict__ in, const float* __restrict__ off,
    __half* __restrict__ cols, int C, int G, int Din, int Hin, int Win,
    int stride, int ncdhw) {
    __shared__ float sbuf[216 * 33];
    int K = C * 27;
    int tid = threadIdx.x;
    int nsl = tid & 31, tap = tid >> 5;
    int nsb = blockIdx.x * 32, g = blockIdx.y;
    int ns = nsb + nsl;
    int n = ns / S_OUT, s = ns % S_OUT;
    int od = s / (OH * OW), oh = (s / OW) % OH, ow = s % OW;
    int kd = tap / 9, kh = (tap / 3) % 3, kw = tap % 3;

    size_t ob = ((size_t)(g * 3) * 27 + tap) * NS + ns;
    float pd = off[ob]                   + (float)(od * stride - 1 + kd);
    float ph = off[ob + (size_t)27 * NS] + (float)(oh * stride - 1 + kh);
    float pw = off[ob + (size_t)54 * NS] + (float)(ow * stride - 1 + kw);
    float d0f = floorf(pd), h0f = floorf(ph), w0f = floorf(pw);
    int d0 = (int)d0f, h0 = (int)h0f, w0 = (int)w0f;
    float fd = pd - d0f, fh = ph - h0f, fw = pw - w0f;

    float wt8[8]; int idx8[8];
    int Sin = Din * Hin * Win;
#pragma unroll
    for (int cr = 0; cr < 8; cr++) {
        int cd = cr >> 2, ch = (cr >> 1) & 1, cw = cr & 1;
        int di = d0 + cd, hi = h0 + ch, wi = w0 + cw;
        bool valid = (di >= 0) && (di < Din) && (hi >= 0) && (hi < Hin) &&
                     (wi >= 0) && (wi < Win);
        float wt = (cd ? fd : 1.f - fd) * (ch ? fh : 1.f - fh) * (cw ? fw : 1.f - fw);
        wt8[cr] = valid ? wt : 0.f;
        int dic = di < 0 ? 0 : (di > Din - 1 ? Din - 1 : di);
        int hic = hi < 0 ? 0 : (hi > Hin - 1 ? Hin - 1 : hi);
        int wic = wi < 0 ? 0 : (wi > Win - 1 ? Win - 1 : wi);
        idx8[cr] = (dic * Hin + hic) * Win + wic;
    }
#pragma unroll
    for (int cc = 0; cc < 8; cc++) {
        int c = g * 8 + cc;
        size_t base = ncdhw ? ((size_t)(n * C + c)) * Sin : ((size_t)c * NBATCH + n) * Sin;
        const __half* bp = in + base;
        float acc = 0.f;
#pragma unroll
        for (int cr = 0; cr < 8; cr++) acc += wt8[cr] * __half2float(bp[idx8[cr]]);
        sbuf[(cc * 27 + tap) * 33 + nsl] = acc;
    }
    __syncthreads();
#pragma unroll
    for (int it = 0; it < 2; it++) {
        int j = it * 864 + tid;
        int nsi = j / 54, kq = j % 54;
        __half2 h0 = __floats2half2_rn(sbuf[(kq * 4 + 0) * 33 + nsi],
                                       sbuf[(kq * 4 + 1) * 33 + nsi]);
        __half2 h1 = __floats2half2_rn(sbuf[(kq * 4 + 2) * 33 + nsi],
                                       sbuf[(kq * 4 + 3) * 33 + nsi]);
        *(uint2*)&cols[(size_t)(nsb + nsi) * K + g * 216 + kq * 4] =
            make_uint2(h2_as_u32(h0), h2_as_u32(h1));
    }
}

// ---------------------------------------------------------------------------
// FP16 mma.sync GEMM: C[M][NS] = A[M][K]*B^T (+bias). BM=128, BN {128,256},
// BK=32, 4-stage cp.async (3 in flight), one sync per k-tile, 8 warps 2x4.
// ---------------------------------------------------------------------------
#define HBK 32
#define HPH 40
#define GST 4

__device__ __forceinline__ void cpasync16h(__half* dst, const __half* src, bool pred) {
    uint32_t d = (uint32_t)__cvta_generic_to_shared(dst);
    int sz = pred ? 16 : 0;
    asm volatile("cp.async.cg.shared.global [%0], [%1], 16, %2;\n"
                 :: "r"(d), "l"(src), "r"(sz));
}
__device__ __forceinline__ void mma_f16(float* c, uint32_t a0, uint32_t a1,
                                        uint32_t a2, uint32_t a3,
                                        uint32_t b0, uint32_t b1) {
    asm volatile(
        "mma.sync.aligned.m16n8k16.row.col.f32.f16.f16.f32 "
        "{%0,%1,%2,%3}, {%4,%5,%6,%7}, {%8,%9}, {%0,%1,%2,%3};\n"
        : "+f"(c[0]), "+f"(c[1]), "+f"(c[2]), "+f"(c[3])
        : "r"(a0), "r"(a1), "r"(a2), "r"(a3), "r"(b0), "r"(b1));
}

template <int BN>
__global__ __launch_bounds__(256) void gemm_h(
    const __half* __restrict__ A, const __half* __restrict__ B,
    const float* __restrict__ bias, float* __restrict__ C, int M, int K) {
    constexpr int BM = 128;
    constexpr int WN = BN / 4;
    constexpr int NT = WN / 8;
    constexpr int AH = BM * HPH;
    constexpr int BH = BN * HPH;
    constexpr int ASL = BM * HBK / 8 / 256;
    constexpr int BSL = BN * HBK / 8 / 256;

    extern __shared__ __half smh[];
    __half* Asm = smh;
    __half* Bsm = smh + GST * AH;

    int tid = threadIdx.x;
    int warp = tid >> 5, lane = tid & 31;
    int wm = warp >> 2, wn = warp & 3;
    int rg = lane >> 2, cg = lane & 3;
    int row0 = blockIdx.x * BM;
    int col0 = blockIdx.y * BN;
    int T = K / HBK;

    int am[ASL], akq[ASL]; bool aok[ASL];
    const __half* asrc[ASL];
#pragma unroll
    for (int u = 0; u < ASL; u++) {
        int slot = u * 256 + tid;
        am[u] = slot >> 2; akq[u] = slot & 3;
        int gm = row0 + am[u];
        aok[u] = gm < M;
        asrc[u] = A + (size_t)(aok[u] ? gm : 0) * K + akq[u] * 8;
    }
    int bn_[BSL], bkq[BSL];
    const __half* bsrc[BSL];
#pragma unroll
    for (int u = 0; u < BSL; u++) {
        int slot = u * 256 + tid;
        bn_[u] = slot >> 2; bkq[u] = slot & 3;
        bsrc[u] = B + (size_t)(col0 + bn_[u]) * K + bkq[u] * 8;
    }

    float acc[4][NT][4];
#pragma unroll
    for (int i = 0; i < 4; i++)
#pragma unroll
        for (int j = 0; j < NT; j++)
#pragma unroll
            for (int r = 0; r < 4; r++) acc[i][j][r] = 0.f;

    // prologue: tiles 0..2 -> stages 0..2
#pragma unroll
    for (int t = 0; t < GST - 1; t++) {
#pragma unroll
        for (int u = 0; u < ASL; u++)
            cpasync16h(&Asm[t * AH + am[u] * HPH + akq[u] * 8], asrc[u] + t * HBK, aok[u]);
#pragma unroll
        for (int u = 0; u < BSL; u++)
            cpasync16h(&Bsm[t * BH + bn_[u] * HPH + bkq[u] * 8], bsrc[u] + t * HBK, true);
        asm volatile("cp.async.commit_group;\n");
    }

    for (int t = 0; t < T; t++) {
        asm volatile("cp.async.wait_group 2;\n");
        __syncthreads();
        int st = t % GST;
        const uint32_t* As32 = (const uint32_t*)(Asm + st * AH);
        const uint32_t* Bs32 = (const uint32_t*)(Bsm + st * BH);
#pragma unroll
        for (int ks = 0; ks < 2; ks++) {
            int kw = ks * 8 + cg;
            uint32_t af[4][4];
#pragma unroll
            for (int i = 0; i < 4; i++) {
                int mb = wm * 64 + i * 16;
                af[i][0] = As32[(mb + rg) * 20 + kw];
                af[i][1] = As32[(mb + 8 + rg) * 20 + kw];
                af[i][2] = As32[(mb + rg) * 20 + kw + 4];
                af[i][3] = As32[(mb + 8 + rg) * 20 + kw + 4];
            }
            uint32_t bf[NT][2];
#pragma unroll
            for (int j = 0; j < NT; j++) {
                int nb = wn * WN + j * 8 + rg;
                bf[j][0] = Bs32[nb * 20 + kw];
                bf[j][1] = Bs32[nb * 20 + kw + 4];
            }
#pragma unroll
            for (int i = 0; i < 4; i++)
#pragma unroll
                for (int j = 0; j < NT; j++)
                    mma_f16(acc[i][j], af[i][0], af[i][1], af[i][2], af[i][3],
                            bf[j][0], bf[j][1]);
        }
        int tn = t + GST - 1;
        if (tn < T) {
            int sn = tn % GST;
            int k0 = tn * HBK;
#pragma unroll
            for (int u = 0; u < ASL; u++)
                cpasync16h(&Asm[sn * AH + am[u] * HPH + akq[u] * 8], asrc[u] + k0, aok[u]);
#pragma unroll
            for (int u = 0; u < BSL; u++)
                cpasync16h(&Bsm[sn * BH + bn_[u] * HPH + bkq[u] * 8], bsrc[u] + k0, true);
        }
        asm volatile("cp.async.commit_group;\n");
    }

#pragma unroll
    for (int i = 0; i < 4; i++) {
        int gm0 = row0 + wm * 64 + i * 16 + rg;
        int gm1 = gm0 + 8;
        float bv0 = (bias && gm0 < M) ? bias[gm0] : 0.f;
        float bv1 = (bias && gm1 < M) ? bias[gm1] : 0.f;
#pragma unroll
        for (int j = 0; j < NT; j++) {
            int gc = col0 + wn * WN + j * 8 + 2 * cg;
            if (gm0 < M)
                *(float2*)&C[(size_t)gm0 * NS + gc] =
                    make_float2(acc[i][j][0] + bv0, acc[i][j][1] + bv0);
            if (gm1 < M)
                *(float2*)&C[(size_t)gm1 * NS + gc] =
                    make_float2(acc[i][j][2] + bv1, acc[i][j][3] + bv1);
        }
    }
}

#define SMEMH256 (GST * (128 * HPH + 256 * HPH) * 2)   // 122880
#define SMEMH128 (GST * (128 * HPH + 128 * HPH) * 2)   // 81920

// ---------------- BN stats / final ----------------
__global__ void bn_stats(const float* __restrict__ x, float* __restrict__ mean,
                         float* __restrict__ istd) {
    int c = blockIdx.x;
    const float* row = x + (size_t)c * NS;
    float s = 0.f, s2 = 0.f;
    for (int i = threadIdx.x; i < NS / 4; i += blockDim.x) {
        float4 v = ((const float4*)row)[i];
        s += v.x + v.y + v.z + v.w;
        s2 += v.x * v.x + v.y * v.y + v.z * v.z + v.w * v.w;
    }
    __shared__ float sh[256], sh2[256];
    sh[threadIdx.x] = s; sh2[threadIdx.x] = s2;
    __syncthreads();
    for (int st = 128; st > 0; st >>= 1) {
        if (threadIdx.x < st) {
            sh[threadIdx.x] += sh[threadIdx.x + st];
            sh2[threadIdx.x] += sh2[threadIdx.x + st];
        }
        __syncthreads();
    }
    if (threadIdx.x == 0) {
        float m = sh[0] / (float)NS;
        float var = sh2[0] / (float)NS - m * m;
        mean[c] = m;
        istd[c] = rsqrtf(var + 1e-5f);
    }
}

__global__ void final_kernel(const float* __restrict__ raw, const float* __restrict__ gam,
                             const float* __restrict__ bet, const float* __restrict__ mean,
                             const float* __restrict__ istd, const float* __restrict__ res,
                             float* __restrict__ out) {
    int i = blockIdx.x * blockDim.x + threadIdx.x;
    if (i >= 128 * NS) return;
    int n = i / (128 * S_OUT);
    int co = (i / S_OUT) % 128;
    int s = i % S_OUT;
    float v = (raw[(size_t)co * NS + n * S_OUT + s] - mean[co]) * istd[co] * gam[co] + bet[co];
    v += res[(size_t)(co & 63) * NS + n * S_OUT + s];
    out[i] = fmaxf(v, 0.f);
}

// ---------------- host ----------------
extern "C" void kernel_launch(void* const* d_in, const int* in_sizes, int n_in,
                              void* d_out, int out_size) {
    (void)in_sizes; (void)n_in; (void)out_size;
    const float* x       = (const float*)d_in[0];
    const float* off1_w  = (const float*)d_in[1];
    const float* off1_b  = (const float*)d_in[2];
    const float* conv1_w = (const float*)d_in[3];
    const float* bn1_g   = (const float*)d_in[4];
    const float* bn1_b   = (const float*)d_in[5];
    const float* off2_w  = (const float*)d_in[6];
    const float* off2_b  = (const float*)d_in[7];
    const float* conv2_w = (const float*)d_in[8];
    const float* bn2_g   = (const float*)d_in[9];
    const float* bn2_b   = (const float*)d_in[10];
    float* out = (float*)d_out;

    __half *cols, *wh, *xh, *act;
    float *off1, *off2, *out1, *out2, *res, *mean, *istd;
    cudaGetSymbolAddress((void**)&cols, g_cols);
    cudaGetSymbolAddress((void**)&wh,   g_wh);
    cudaGetSymbolAddress((void**)&xh,   g_xh);
    cudaGetSymbolAddress((void**)&act,  g_act);
    cudaGetSymbolAddress((void**)&off1, g_off1);
    cudaGetSymbolAddress((void**)&off2, g_off2);
    cudaGetSymbolAddress((void**)&out1, g_out1);
    cudaGetSymbolAddress((void**)&out2, g_out2);
    cudaGetSymbolAddress((void**)&res,  g_res);
    cudaGetSymbolAddress((void**)&mean, g_mean);
    cudaGetSymbolAddress((void**)&istd, g_istd);

    static int attr_done = 0;
    if (!attr_done) {
        cudaFuncSetAttribute(gemm_h<256>, cudaFuncAttributeMaxDynamicSharedMemorySize, SMEMH256);
        cudaFuncSetAttribute(gemm_h<128>, cudaFuncAttributeMaxDynamicSharedMemorySize, SMEMH128);
        attr_done = 1;
    }

    const int T = 256;
    const int n4all = (N_OFF1W + N_CV1W + N_OFF2W + N_CV2W) / 4;

    // launch 1: all weights -> half
    f2h_all<<<(n4all + T - 1) / T, T>>>(off1_w, conv1_w, off2_w, conv2_w, wh);
    // launch 2: x -> half
    f2h4_kernel<<<(6422528 / 4 + T - 1) / T, T>>>(x, xh, 6422528 / 4);
    // launch 3: im2col for off1
    im2col_blk<64, 2, 1><<<dim3(NS / 32, 8), 864>>>(xh, cols, 16, 56, 56);
    // launch 4 (profiled by ncu): off1 GEMM, M=648, K=1728
    gemm_h<256><<<dim3(6, NS / 256), 256, SMEMH256>>>(wh + WH_OFF1, cols, off1_b, off1, 648, 1728);
    // launch 5: residual maxpool (independent)
    maxpool_kernel<<<(64 * NS + T - 1) / T, T>>>(x, res);

    // out1 = deform_conv3d(x, off1, stride=2): M=128, K=1728
    deform_T<<<dim3(NS / 32, 8), 864>>>(xh, off1, cols, 64, 8, 16, 56, 56, 2, 1);
    gemm_h<128><<<dim3(1, NS / 128), 256, SMEMH128>>>(wh + WH_CV1, cols, nullptr, out1, 128, 1728);

    bn_stats<<<128, 256>>>(out1, mean, istd);
    bn_act_h<<<(128 * NS / 4 + T - 1) / T, T>>>(out1, act, bn1_g, bn1_b, mean, istd);

    // off2 = conv3d(act, stride=1): M=1296, K=3456
    im2col_blk<128, 1, 0><<<dim3(NS / 32, 16), 864>>>(act, cols, 8, 28, 28);
    gemm_h<256><<<dim3(11, NS / 256), 256, SMEMH256>>>(wh + WH_OFF2, cols, off2_b, off2, 1296, 3456);

    // out2 = deform_conv3d(act, off2, stride=1): M=128, K=3456
    deform_T<<<dim3(NS / 32, 16), 864>>>(act, off2, cols, 128, 16, 8, 28, 28, 1, 0);
    gemm_h<128><<<dim3(1, NS / 128), 256, SMEMH128>>>(wh + WH_CV2, cols, nullptr, out2, 128, 3456);

    bn_stats<<<128, 256>>>(out2, mean, istd);
    final_kernel<<<(128 * NS + T - 1) / T, T>>>(out2, bn2_g, bn2_b, mean, istd, res, out);
}

// round 13
// speedup vs baseline: 1.7380x; 1.0246x over previous
#include <cuda_runtime.h>
#include <cuda_fp16.h>
#include <math.h>
#include <stdint.h>

#define NBATCH 2
#define OD 8
#define OH 28
#define OW 28
#define S_OUT 6272
#define NS 12544

__device__ __half g_cols[43352064];  // [ns][K], max K=3456
__device__ __half g_wh[6262272];     // all four weight sets, half
__device__ __half g_xh[6422528];     // x as half (NCDHW)
__device__ __half g_act[1605632];    // relu(bn1(out1)) as half, [c][NS]
__device__ float g_off1[8128512];    // [648][NS]
__device__ float g_off2[16257024];   // [1296][NS]
__device__ float g_out1[1605632];    // [128][NS]  (raw, pre-BN)
__device__ float g_out2[1605632];
__device__ float g_res[802816];      // [64][NS]
__device__ float g_mean[128];
__device__ float g_istd[128];

#define WH_OFF1 0
#define WH_CV1  1119744
#define WH_OFF2 1340928
#define WH_CV2  5819904
#define N_OFF1W 1119744
#define N_CV1W  221184
#define N_OFF2W 4478976
#define N_CV2W  442368

__device__ __forceinline__ uint32_t h2_as_u32(__half2 h) {
    return *(uint32_t*)&h;
}

// ---------------- all four weight sets fp32 -> fp16, one launch ----------------
__global__ void f2h_all(const float* __restrict__ w0, const float* __restrict__ w1,
                        const float* __restrict__ w2, const float* __restrict__ w3,
                        __half* __restrict__ out) {
    const int n40 = N_OFF1W / 4, n41 = N_CV1W / 4, n42 = N_OFF2W / 4, n43 = N_CV2W / 4;
    int i = blockIdx.x * blockDim.x + threadIdx.x;
    const float* src;
    int li;
    __half* dst;
    if (i < n40)                { src = w0; li = i;               dst = out + WH_OFF1; }
    else if (i < n40+n41)       { src = w1; li = i - n40;         dst = out + WH_CV1; }
    else if (i < n40+n41+n42)   { src = w2; li = i - n40-n41;     dst = out + WH_OFF2; }
    else if (i < n40+n41+n42+n43){ src = w3; li = i - n40-n41-n42; dst = out + WH_CV2; }
    else return;
    float4 v = ((const float4*)src)[li];
    __half2 h0 = __floats2half2_rn(v.x, v.y);
    __half2 h1 = __floats2half2_rn(v.z, v.w);
    ((uint2*)dst)[li] = make_uint2(h2_as_u32(h0), h2_as_u32(h1));
}

// ---------------- fp32 -> fp16, vectorized x4 ----------------
__global__ void f2h4_kernel(const float* __restrict__ in, __half* __restrict__ out, int n4) {
    int i = blockIdx.x * blockDim.x + threadIdx.x;
    if (i >= n4) return;
    float4 v = ((const float4*)in)[i];
    __half2 h0 = __floats2half2_rn(v.x, v.y);
    __half2 h1 = __floats2half2_rn(v.z, v.w);
    ((uint2*)out)[i] = make_uint2(h2_as_u32(h0), h2_as_u32(h1));
}

// ---------------- BN+relu -> fp16 act, vectorized x4 ----------------
__global__ void bn_act_h(const float* __restrict__ in, __half* __restrict__ out,
                         const float* __restrict__ gam, const float* __restrict__ bet,
                         const float* __restrict__ mean, const float* __restrict__ istd) {
    int i = blockIdx.x * blockDim.x + threadIdx.x;
    if (i >= 128 * NS / 4) return;
    int c = (i * 4) / NS;
    float sc = gam[c] * istd[c];
    float sh = bet[c] - mean[c] * sc;
    float4 v = ((const float4*)in)[i];
    v.x = fmaxf(sc * v.x + sh, 0.f);
    v.y = fmaxf(sc * v.y + sh, 0.f);
    v.z = fmaxf(sc * v.z + sh, 0.f);
    v.w = fmaxf(sc * v.w + sh, 0.f);
    __half2 h0 = __floats2half2_rn(v.x, v.y);
    __half2 h1 = __floats2half2_rn(v.z, v.w);
    ((uint2*)out)[i] = make_uint2(h2_as_u32(h0), h2_as_u32(h1));
}

// ---------------- maxpool (fp32 x -> fp32 residual, exact path) ----------------
__global__ void maxpool_kernel(const float* __restrict__ x, float* __restrict__ res) {
    int i = blockIdx.x * blockDim.x + threadIdx.x;
    if (i >= 64 * NS) return;
    int ns = i % NS, c = i / NS;
    int n = ns / S_OUT, s = ns % S_OUT;
    int od = s / (OH * OW), oh = (s / OW) % OH, ow = s % OW;
    const float* xp = x + ((size_t)(n * 64 + c)) * 16 * 56 * 56;
    int d0 = od * 2 - 1, h0 = oh * 2 - 1, w0 = ow * 2 - 1;
    int dlo = d0 < 0 ? 0 : d0, dhi = d0 + 2 > 15 ? 15 : d0 + 2;
    int hlo = h0 < 0 ? 0 : h0, hhi = h0 + 2 > 55 ? 55 : h0 + 2;
    int wlo = w0 < 0 ? 0 : w0, whi = w0 + 2 > 55 ? 55 : w0 + 2;
    float m = -INFINITY;
    for (int dd = dlo; dd <= dhi; dd++)
        for (int hh = hlo; hh <= hhi; hh++)
            for (int ww = wlo; ww <= whi; ww++)
                m = fmaxf(m, xp[(dd * 56 + hh) * 56 + ww]);
    res[(size_t)c * NS + ns] = m;
}

// ---------------------------------------------------------------------------
// Block-staged im2col (fp16 input) -> cols[ns][K] (half).
// ---------------------------------------------------------------------------
template <int C, int STRIDE, int NCDHW>
__global__ __launch_bounds__(864) void im2col_blk(
    const __half* __restrict__ in, __half* __restrict__ cols,
    int Din, int Hin, int Win) {
    __shared__ float sbuf[216 * 33];
    const int K = C * 27;
    int tid = threadIdx.x;
    int nsl = tid & 31, tap = tid >> 5;
    int nsb = blockIdx.x * 32, g = blockIdx.y;
    int ns = nsb + nsl;
    int n = ns / S_OUT, s = ns % S_OUT;
    int od = s / (OH * OW), oh = (s / OW) % OH, ow = s % OW;
    int kd = tap / 9, kh = (tap / 3) % 3, kw = tap % 3;
    int id = od * STRIDE - 1 + kd, ih = oh * STRIDE - 1 + kh, iw = ow * STRIDE - 1 + kw;
    bool valid = id >= 0 && id < Din && ih >= 0 && ih < Hin && iw >= 0 && iw < Win;
    int Sin = Din * Hin * Win;
    int sidx = valid ? (id * Hin + ih) * Win + iw : 0;

#pragma unroll
    for (int cc = 0; cc < 8; cc++) {
        int c = g * 8 + cc;
        size_t base = NCDHW ? ((size_t)(n * C + c)) * Sin : ((size_t)c * NBATCH + n) * Sin;
        float v = valid ? __half2float(in[base + sidx]) : 0.f;
        sbuf[(cc * 27 + tap) * 33 + nsl] = v;
    }
    __syncthreads();
#pragma unroll
    for (int it = 0; it < 2; it++) {
        int j = it * 864 + tid;
        int nsi = j / 54, kq = j % 54;
        __half2 h0 = __floats2half2_rn(sbuf[(kq * 4 + 0) * 33 + nsi],
                                       sbuf[(kq * 4 + 1) * 33 + nsi]);
        __half2 h1 = __floats2half2_rn(sbuf[(kq * 4 + 2) * 33 + nsi],
                                       sbuf[(kq * 4 + 3) * 33 + nsi]);
        *(uint2*)&cols[(size_t)(nsb + nsi) * K + g * 216 + kq * 4] =
            make_uint2(h2_as_u32(h0), h2_as_u32(h1));
    }
}

// ---------------------------------------------------------------------------
// Deformable im2col (fp16 input) -> cols[ns][K] (half), smem staged.
// ---------------------------------------------------------------------------
__global__ __launch_bounds__(864) void deform_T(
    const __half* __restrict__ in, const float* __restrict__ off,
    __half* __restrict__ cols, int C, int G, int Din, int Hin, int Win,
    int stride, int ncdhw) {
    __shared__ float sbuf[216 * 33];
    int K = C * 27;
    int tid = threadIdx.x;
    int nsl = tid & 31, tap = tid >> 5;
    int nsb = blockIdx.x * 32, g = blockIdx.y;
    int ns = nsb + nsl;
    int n = ns / S_OUT, s = ns % S_OUT;
    int od = s / (OH * OW), oh = (s / OW) % OH, ow = s % OW;
    int kd = tap / 9, kh = (tap / 3) % 3, kw = tap % 3;

    size_t ob = ((size_t)(g * 3) * 27 + tap) * NS + ns;
    float pd = off[ob]                   + (float)(od * stride - 1 + kd);
    float ph = off[ob + (size_t)27 * NS] + (float)(oh * stride - 1 + kh);
    float pw = off[ob + (size_t)54 * NS] + (float)(ow * stride - 1 + kw);
    float d0f = floorf(pd), h0f = floorf(ph), w0f = floorf(pw);
    int d0 = (int)d0f, h0 = (int)h0f, w0 = (int)w0f;
    float fd = pd - d0f, fh = ph - h0f, fw = pw - w0f;

    float wt8[8]; int idx8[8];
    int Sin = Din * Hin * Win;
#pragma unroll
    for (int cr = 0; cr < 8; cr++) {
        int cd = cr >> 2, ch = (cr >> 1) & 1, cw = cr & 1;
        int di = d0 + cd, hi = h0 + ch, wi = w0 + cw;
        bool valid = (di >= 0) && (di < Din) && (hi >= 0) && (hi < Hin) &&
                     (wi >= 0) && (wi < Win);
        float wt = (cd ? fd : 1.f - fd) * (ch ? fh : 1.f - fh) * (cw ? fw : 1.f - fw);
        wt8[cr] = valid ? wt : 0.f;
        int dic = di < 0 ? 0 : (di > Din - 1 ? Din - 1 : di);
        int hic = hi < 0 ? 0 : (hi > Hin - 1 ? Hin - 1 : hi);
        int wic = wi < 0 ? 0 : (wi > Win - 1 ? Win - 1 : wi);
        idx8[cr] = (dic * Hin + hic) * Win + wic;
    }
#pragma unroll
    for (int cc = 0; cc < 8; cc++) {
        int c = g * 8 + cc;
        size_t base = ncdhw ? ((size_t)(n * C + c)) * Sin : ((size_t)c * NBATCH + n) * Sin;
        const __half* bp = in + base;
        float acc = 0.f;
#pragma unroll
        for (int cr = 0; cr < 8; cr++) acc += wt8[cr] * __half2float(bp[idx8[cr]]);
        sbuf[(cc * 27 + tap) * 33 + nsl] = acc;
    }
    __syncthreads();
#pragma unroll
    for (int it = 0; it < 2; it++) {
        int j = it * 864 + tid;
        int nsi = j / 54, kq = j % 54;
        __half2 h0 = __floats2half2_rn(sbuf[(kq * 4 + 0) * 33 + nsi],
                                       sbuf[(kq * 4 + 1) * 33 + nsi]);
        __half2 h1 = __floats2half2_rn(sbuf[(kq * 4 + 2) * 33 + nsi],
                                       sbuf[(kq * 4 + 3) * 33 + nsi]);
        *(uint2*)&cols[(size_t)(nsb + nsi) * K + g * 216 + kq * 4] =
            make_uint2(h2_as_u32(h0), h2_as_u32(h1));
    }
}

// ---------------------------------------------------------------------------
// FP16 mma.sync GEMM with ldmatrix fragment loads.
// C[M][NS] = A[M][K]*B^T (+bias). BM=128, BN {128,256}, BK=32,
// 4-stage cp.async (3 in flight), one sync per k-tile, 8 warps 2x4.
// ---------------------------------------------------------------------------
#define HBK 32
#define HPH 40
#define GST 4

__device__ __forceinline__ void cpasync16h(__half* dst, const __half* src, bool pred) {
    uint32_t d = (uint32_t)__cvta_generic_to_shared(dst);
    int sz = pred ? 16 : 0;
    asm volatile("cp.async.cg.shared.global [%0], [%1], 16, %2;\n"
                 :: "r"(d), "l"(src), "r"(sz));
}
__device__ __forceinline__ void mma_f16(float* c, uint32_t a0, uint32_t a1,
                                        uint32_t a2, uint32_t a3,
                                        uint32_t b0, uint32_t b1) {
    asm volatile(
        "mma.sync.aligned.m16n8k16.row.col.f32.f16.f16.f32 "
        "{%0,%1,%2,%3}, {%4,%5,%6,%7}, {%8,%9}, {%0,%1,%2,%3};\n"
        : "+f"(c[0]), "+f"(c[1]), "+f"(c[2]), "+f"(c[3])
        : "r"(a0), "r"(a1), "r"(a2), "r"(a3), "r"(b0), "r"(b1));
}
__device__ __forceinline__ void ldsm_x4(uint32_t* r, uint32_t addr) {
    asm volatile("ldmatrix.sync.aligned.m8n8.x4.shared.b16 {%0,%1,%2,%3}, [%4];"
                 : "=r"(r[0]), "=r"(r[1]), "=r"(r[2]), "=r"(r[3]) : "r"(addr));
}

template <int BN>
__global__ __launch_bounds__(256) void gemm_h(
    const __half* __restrict__ A, const __half* __restrict__ B,
    const float* __restrict__ bias, float* __restrict__ C, int M, int K) {
    constexpr int BM = 128;
    constexpr int WN = BN / 4;      // 64 or 32
    constexpr int NT = WN / 8;      // 8 or 4
    constexpr int NB2 = NT / 2;     // B ldsm.x4 per ks: 4 or 2
    constexpr int AH = BM * HPH;    // halves per A stage
    constexpr int BH = BN * HPH;
    constexpr int ASL = BM * HBK / 8 / 256;
    constexpr int BSL = BN * HBK / 8 / 256;

    extern __shared__ __half smh[];
    __half* Asm = smh;
    __half* Bsm = smh + GST * AH;

    int tid = threadIdx.x;
    int warp = tid >> 5, lane = tid & 31;
    int wm = warp >> 2, wn = warp & 3;
    int rg = lane >> 2, cg = lane & 3;
    int row0 = blockIdx.x * BM;
    int col0 = blockIdx.y * BN;
    int T = K / HBK;

    // cp.async slot geometry
    int am[ASL], akq[ASL]; bool aok[ASL];
    const __half* asrc[ASL];
#pragma unroll
    for (int u = 0; u < ASL; u++) {
        int slot = u * 256 + tid;
        am[u] = slot >> 2; akq[u] = slot & 3;
        int gm = row0 + am[u];
        aok[u] = gm < M;
        asrc[u] = A + (size_t)(aok[u] ? gm : 0) * K + akq[u] * 8;
    }
    int bn_[BSL], bkq[BSL];
    const __half* bsrc[BSL];
#pragma unroll
    for (int u = 0; u < BSL; u++) {
        int slot = u * 256 + tid;
        bn_[u] = slot >> 2; bkq[u] = slot & 3;
        bsrc[u] = B + (size_t)(col0 + bn_[u]) * K + bkq[u] * 8;
    }

    // ldmatrix per-thread byte offsets within a stage (ks=0; ks=1 adds 32B)
    uint32_t aBase = (uint32_t)__cvta_generic_to_shared(Asm);
    uint32_t bBase = (uint32_t)__cvta_generic_to_shared(Bsm);
    uint32_t aOff[4];
#pragma unroll
    for (int i = 0; i < 4; i++) {
        int row = wm * 64 + i * 16 + (lane & 15);
        int col = (lane >> 4) << 3;           // 0 or 8 halves
        aOff[i] = (uint32_t)((row * HPH + col) * 2);
    }
    uint32_t bOff[NB2];
#pragma unroll
    for (int p = 0; p < NB2; p++) {
        int row = wn * WN + p * 16 + (lane & 7) + ((lane & 16) ? 8 : 0);
        int col = (lane & 8) ? 8 : 0;         // halves
        bOff[p] = (uint32_t)((row * HPH + col) * 2);
    }

    float acc[4][NT][4];
#pragma unroll
    for (int i = 0; i < 4; i++)
#pragma unroll
        for (int j = 0; j < NT; j++)
#pragma unroll
            for (int r = 0; r < 4; r++) acc[i][j][r] = 0.f;

    // prologue: tiles 0..GST-2
#pragma unroll
    for (int t = 0; t < GST - 1; t++) {
#pragma unroll
        for (int u = 0; u < ASL; u++)
            cpasync16h(&Asm[t * AH + am[u] * HPH + akq[u] * 8], asrc[u] + t * HBK, aok[u]);
#pragma unroll
        for (int u = 0; u < BSL; u++)
            cpasync16h(&Bsm[t * BH + bn_[u] * HPH + bkq[u] * 8], bsrc[u] + t * HBK, true);
        asm volatile("cp.async.commit_group;\n");
    }

    for (int t = 0; t < T; t++) {
        asm volatile("cp.async.wait_group 2;\n");
        __syncthreads();
        int st = t % GST;
        uint32_t aS = aBase + (uint32_t)(st * AH * 2);
        uint32_t bS = bBase + (uint32_t)(st * BH * 2);

        // load ALL fragments for this k-tile (both k16 halves) via ldmatrix
        uint32_t af[2][4][4], bf[2][NB2][4];
#pragma unroll
        for (int ks = 0; ks < 2; ks++) {
            uint32_t kadd = ks * 32;   // 16 halves = 32 bytes
#pragma unroll
            for (int i = 0; i < 4; i++) ldsm_x4(af[ks][i], aS + aOff[i] + kadd);
#pragma unroll
            for (int p = 0; p < NB2; p++) ldsm_x4(bf[ks][p], bS + bOff[p] + kadd);
        }
        // 64 MMAs
#pragma unroll
        for (int ks = 0; ks < 2; ks++)
#pragma unroll
            for (int i = 0; i < 4; i++)
#pragma unroll
                for (int p = 0; p < NB2; p++) {
                    mma_f16(acc[i][2 * p],     af[ks][i][0], af[ks][i][1],
                            af[ks][i][2], af[ks][i][3], bf[ks][p][0], bf[ks][p][1]);
                    mma_f16(acc[i][2 * p + 1], af[ks][i][0], af[ks][i][1],
                            af[ks][i][2], af[ks][i][3], bf[ks][p][2], bf[ks][p][3]);
                }

        int tn = t + GST - 1;
        if (tn < T) {
            int sn = tn % GST;
            int k0 = tn * HBK;
#pragma unroll
            for (int u = 0; u < ASL; u++)
                cpasync16h(&Asm[sn * AH + am[u] * HPH + akq[u] * 8], asrc[u] + k0, aok[u]);
#pragma unroll
            for (int u = 0; u < BSL; u++)
                cpasync16h(&Bsm[sn * BH + bn_[u] * HPH + bkq[u] * 8], bsrc[u] + k0, true);
        }
        asm volatile("cp.async.commit_group;\n");
    }

    // epilogue
#pragma unroll
    for (int i = 0; i < 4; i++) {
        int gm0 = row0 + wm * 64 + i * 16 + rg;
        int gm1 = gm0 + 8;
        float bv0 = (bias && gm0 < M) ? bias[gm0] : 0.f;
        float bv1 = (bias && gm1 < M) ? bias[gm1] : 0.f;
#pragma unroll
        for (int j = 0; j < NT; j++) {
            int gc = col0 + wn * WN + j * 8 + 2 * cg;
            if (gm0 < M)
                *(float2*)&C[(size_t)gm0 * NS + gc] =
                    make_float2(acc[i][j][0] + bv0, acc[i][j][1] + bv0);
            if (gm1 < M)
                *(float2*)&C[(size_t)gm1 * NS + gc] =
                    make_float2(acc[i][j][2] + bv1, acc[i][j][3] + bv1);
        }
    }
}

#define SMEMH256 (GST * (128 * HPH + 256 * HPH) * 2)   // 122880
#define SMEMH128 (GST * (128 * HPH + 128 * HPH) * 2)   // 81920

// ---------------- BN stats / final ----------------
__global__ void bn_stats(const float* __restrict__ x, float* __restrict__ mean,
                         float* __restrict__ istd) {
    int c = blockIdx.x;
    const float* row = x + (size_t)c * NS;
    float s = 0.f, s2 = 0.f;
    for (int i = threadIdx.x; i < NS / 4; i += blockDim.x) {
        float4 v = ((const float4*)row)[i];
        s += v.x + v.y + v.z + v.w;
        s2 += v.x * v.x + v.y * v.y + v.z * v.z + v.w * v.w;
    }
    __shared__ float sh[256], sh2[256];
    sh[threadIdx.x] = s; sh2[threadIdx.x] = s2;
    __syncthreads();
    for (int st = 128; st > 0; st >>= 1) {
        if (threadIdx.x < st) {
            sh[threadIdx.x] += sh[threadIdx.x + st];
            sh2[threadIdx.x] += sh2[threadIdx.x + st];
        }
        __syncthreads();
    }
    if (threadIdx.x == 0) {
        float m = sh[0] / (float)NS;
        float var = sh2[0] / (float)NS - m * m;
        mean[c] = m;
        istd[c] = rsqrtf(var + 1e-5f);
    }
}

__global__ void final_kernel(const float* __restrict__ raw, const float* __restrict__ gam,
                             const float* __restrict__ bet, const float* __restrict__ mean,
                             const float* __restrict__ istd, const float* __restrict__ res,
                             float* __restrict__ out) {
    int i = blockIdx.x * blockDim.x + threadIdx.x;
    if (i >= 128 * NS) return;
    int n = i / (128 * S_OUT);
    int co = (i / S_OUT) % 128;
    int s = i % S_OUT;
    float v = (raw[(size_t)co * NS + n * S_OUT + s] - mean[co]) * istd[co] * gam[co] + bet[co];
    v += res[(size_t)(co & 63) * NS + n * S_OUT + s];
    out[i] = fmaxf(v, 0.f);
}

// ---------------- host ----------------
extern "C" void kernel_launch(void* const* d_in, const int* in_sizes, int n_in,
                              void* d_out, int out_size) {
    (void)in_sizes; (void)n_in; (void)out_size;
    const float* x       = (const float*)d_in[0];
    const float* off1_w  = (const float*)d_in[1];
    const float* off1_b  = (const float*)d_in[2];
    const float* conv1_w = (const float*)d_in[3];
    const float* bn1_g   = (const float*)d_in[4];
    const float* bn1_b   = (const float*)d_in[5];
    const float* off2_w  = (const float*)d_in[6];
    const float* off2_b  = (const float*)d_in[7];
    const float* conv2_w = (const float*)d_in[8];
    const float* bn2_g   = (const float*)d_in[9];
    const float* bn2_b   = (const float*)d_in[10];
    float* out = (float*)d_out;

    __half *cols, *wh, *xh, *act;
    float *off1, *off2, *out1, *out2, *res, *mean, *istd;
    cudaGetSymbolAddress((void**)&cols, g_cols);
    cudaGetSymbolAddress((void**)&wh,   g_wh);
    cudaGetSymbolAddress((void**)&xh,   g_xh);
    cudaGetSymbolAddress((void**)&act,  g_act);
    cudaGetSymbolAddress((void**)&off1, g_off1);
    cudaGetSymbolAddress((void**)&off2, g_off2);
    cudaGetSymbolAddress((void**)&out1, g_out1);
    cudaGetSymbolAddress((void**)&out2, g_out2);
    cudaGetSymbolAddress((void**)&res,  g_res);
    cudaGetSymbolAddress((void**)&mean, g_mean);
    cudaGetSymbolAddress((void**)&istd, g_istd);

    static int attr_done = 0;
    if (!attr_done) {
        cudaFuncSetAttribute(gemm_h<256>, cudaFuncAttributeMaxDynamicSharedMemorySize, SMEMH256);
        cudaFuncSetAttribute(gemm_h<128>, cudaFuncAttributeMaxDynamicSharedMemorySize, SMEMH128);
        attr_done = 1;
    }

    const int T = 256;
    const int n4all = (N_OFF1W + N_CV1W + N_OFF2W + N_CV2W) / 4;

    // launch 1: all weights -> half
    f2h_all<<<(n4all + T - 1) / T, T>>>(off1_w, conv1_w, off2_w, conv2_w, wh);
    // launch 2: x -> half
    f2h4_kernel<<<(6422528 / 4 + T - 1) / T, T>>>(x, xh, 6422528 / 4);
    // launch 3: im2col for off1
    im2col_blk<64, 2, 1><<<dim3(NS / 32, 8), 864>>>(xh, cols, 16, 56, 56);
    // launch 4 (profiled by ncu): off1 GEMM, M=648, K=1728
    gemm_h<256><<<dim3(6, NS / 256), 256, SMEMH256>>>(wh + WH_OFF1, cols, off1_b, off1, 648, 1728);
    // launch 5: residual maxpool (independent)
    maxpool_kernel<<<(64 * NS + T - 1) / T, T>>>(x, res);

    // out1 = deform_conv3d(x, off1, stride=2): M=128, K=1728
    deform_T<<<dim3(NS / 32, 8), 864>>>(xh, off1, cols, 64, 8, 16, 56, 56, 2, 1);
    gemm_h<128><<<dim3(1, NS / 128), 256, SMEMH128>>>(wh + WH_CV1, cols, nullptr, out1, 128, 1728);

    bn_stats<<<128, 256>>>(out1, mean, istd);
    bn_act_h<<<(128 * NS / 4 + T - 1) / T, T>>>(out1, act, bn1_g, bn1_b, mean, istd);

    // off2 = conv3d(act, stride=1): M=1296, K=3456
    im2col_blk<128, 1, 0><<<dim3(NS / 32, 16), 864>>>(act, cols, 8, 28, 28);
    gemm_h<256><<<dim3(11, NS / 256), 256, SMEMH256>>>(wh + WH_OFF2, cols, off2_b, off2, 1296, 3456);

    // out2 = deform_conv3d(act, off2, stride=1): M=128, K=3456
    deform_T<<<dim3(NS / 32, 16), 864>>>(act, off2, cols, 128, 16, 8, 28, 28, 1, 0);
    gemm_h<128><<<dim3(1, NS / 128), 256, SMEMH128>>>(wh + WH_CV2, cols, nullptr, out2, 128, 3456);

    bn_stats<<<128, 256>>>(out2, mean, istd);
    final_kernel<<<(128 * NS + T - 1) / T, T>>>(out2, bn2_g, bn2_b, mean, istd, res, out);
}

// round 14
// speedup vs baseline: 1.9190x; 1.1041x over previous
#include <cuda_runtime.h>
#include <cuda_fp16.h>
#include <math.h>
#include <stdint.h>

#define NBATCH 2
#define OD 8
#define OH 28
#define OW 28
#define S_OUT 6272
#define NS 12544

__device__ __half g_cols[43352064];  // [ns][K], max K=3456
__device__ __half g_wh[6262272];     // all four weight sets, half
__device__ __half g_xh[6422528];     // x as half (NCDHW)
__device__ __half g_act[1605632];    // relu(bn1(out1)) as half, [c][NS]
__device__ float g_off1[8128512];    // [648][NS]
__device__ float g_off2[16257024];   // [1296][NS]
__device__ float g_out1[1605632];    // [128][NS]  (raw, pre-BN)
__device__ float g_out2[1605632];
__device__ float g_res[802816];      // [64][NS]
__device__ float g_mean[128];
__device__ float g_istd[128];

#define WH_OFF1 0
#define WH_CV1  1119744
#define WH_OFF2 1340928
#define WH_CV2  5819904
#define N_OFF1W 1119744
#define N_CV1W  221184
#define N_OFF2W 4478976
#define N_CV2W  442368

__device__ __forceinline__ uint32_t h2_as_u32(__half2 h) {
    return *(uint32_t*)&h;
}

// ---------------- all four weight sets fp32 -> fp16, one launch ----------------
__global__ void f2h_all(const float* __restrict__ w0, const float* __restrict__ w1,
                        const float* __restrict__ w2, const float* __restrict__ w3,
                        __half* __restrict__ out) {
    const int n40 = N_OFF1W / 4, n41 = N_CV1W / 4, n42 = N_OFF2W / 4, n43 = N_CV2W / 4;
    int i = blockIdx.x * blockDim.x + threadIdx.x;
    const float* src;
    int li;
    __half* dst;
    if (i < n40)                { src = w0; li = i;               dst = out + WH_OFF1; }
    else if (i < n40+n41)       { src = w1; li = i - n40;         dst = out + WH_CV1; }
    else if (i < n40+n41+n42)   { src = w2; li = i - n40-n41;     dst = out + WH_OFF2; }
    else if (i < n40+n41+n42+n43){ src = w3; li = i - n40-n41-n42; dst = out + WH_CV2; }
    else return;
    float4 v = ((const float4*)src)[li];
    __half2 h0 = __floats2half2_rn(v.x, v.y);
    __half2 h1 = __floats2half2_rn(v.z, v.w);
    ((uint2*)dst)[li] = make_uint2(h2_as_u32(h0), h2_as_u32(h1));
}

// ---------------- fp32 -> fp16, vectorized x4 ----------------
__global__ void f2h4_kernel(const float* __restrict__ in, __half* __restrict__ out, int n4) {
    int i = blockIdx.x * blockDim.x + threadIdx.x;
    if (i >= n4) return;
    float4 v = ((const float4*)in)[i];
    __half2 h0 = __floats2half2_rn(v.x, v.y);
    __half2 h1 = __floats2half2_rn(v.z, v.w);
    ((uint2*)out)[i] = make_uint2(h2_as_u32(h0), h2_as_u32(h1));
}

// ---------------- BN+relu -> fp16 act, vectorized x4 ----------------
__global__ void bn_act_h(const float* __restrict__ in, __half* __restrict__ out,
                         const float* __restrict__ gam, const float* __restrict__ bet,
                         const float* __restrict__ mean, const float* __restrict__ istd) {
    int i = blockIdx.x * blockDim.x + threadIdx.x;
    if (i >= 128 * NS / 4) return;
    int c = (i * 4) / NS;
    float sc = gam[c] * istd[c];
    float sh = bet[c] - mean[c] * sc;
    float4 v = ((const float4*)in)[i];
    v.x = fmaxf(sc * v.x + sh, 0.f);
    v.y = fmaxf(sc * v.y + sh, 0.f);
    v.z = fmaxf(sc * v.z + sh, 0.f);
    v.w = fmaxf(sc * v.w + sh, 0.f);
    __half2 h0 = __floats2half2_rn(v.x, v.y);
    __half2 h1 = __floats2half2_rn(v.z, v.w);
    ((uint2*)out)[i] = make_uint2(h2_as_u32(h0), h2_as_u32(h1));
}

// ---------------- maxpool (fp32 x -> fp32 residual, exact path) ----------------
__global__ void maxpool_kernel(const float* __restrict__ x, float* __restrict__ res) {
    int i = blockIdx.x * blockDim.x + threadIdx.x;
    if (i >= 64 * NS) return;
    int ns = i % NS, c = i / NS;
    int n = ns / S_OUT, s = ns % S_OUT;
    int od = s / (OH * OW), oh = (s / OW) % OH, ow = s % OW;
    const float* xp = x + ((size_t)(n * 64 + c)) * 16 * 56 * 56;
    int d0 = od * 2 - 1, h0 = oh * 2 - 1, w0 = ow * 2 - 1;
    int dlo = d0 < 0 ? 0 : d0, dhi = d0 + 2 > 15 ? 15 : d0 + 2;
    int hlo = h0 < 0 ? 0 : h0, hhi = h0 + 2 > 55 ? 55 : h0 + 2;
    int wlo = w0 < 0 ? 0 : w0, whi = w0 + 2 > 55 ? 55 : w0 + 2;
    float m = -INFINITY;
    for (int dd = dlo; dd <= dhi; dd++)
        for (int hh = hlo; hh <= hhi; hh++)
            for (int ww = wlo; ww <= whi; ww++)
                m = fmaxf(m, xp[(dd * 56 + hh) * 56 + ww]);
    res[(size_t)c * NS + ns] = m;
}

// ---------------------------------------------------------------------------
// Block-staged im2col (fp16 input) -> cols[ns][K] (half).
// ---------------------------------------------------------------------------
template <int C, int STRIDE, int NCDHW>
__global__ __launch_bounds__(864) void im2col_blk(
    const __half* __restrict__ in, __half* __restrict__ cols,
    int Din, int Hin, int Win) {
    __shared__ float sbuf[216 * 33];
    const int K = C * 27;
    int tid = threadIdx.x;
    int nsl = tid & 31, tap = tid >> 5;
    int nsb = blockIdx.x * 32, g = blockIdx.y;
    int ns = nsb + nsl;
    int n = ns / S_OUT, s = ns % S_OUT;
    int od = s / (OH * OW), oh = (s / OW) % OH, ow = s % OW;
    int kd = tap / 9, kh = (tap / 3) % 3, kw = tap % 3;
    int id = od * STRIDE - 1 + kd, ih = oh * STRIDE - 1 + kh, iw = ow * STRIDE - 1 + kw;
    bool valid = id >= 0 && id < Din && ih >= 0 && ih < Hin && iw >= 0 && iw < Win;
    int Sin = Din * Hin * Win;
    int sidx = valid ? (id * Hin + ih) * Win + iw : 0;

#pragma unroll
    for (int cc = 0; cc < 8; cc++) {
        int c = g * 8 + cc;
        size_t base = NCDHW ? ((size_t)(n * C + c)) * Sin : ((size_t)c * NBATCH + n) * Sin;
        float v = valid ? __half2float(in[base + sidx]) : 0.f;
        sbuf[(cc * 27 + tap) * 33 + nsl] = v;
    }
    __syncthreads();
#pragma unroll
    for (int it = 0; it < 2; it++) {
        int j = it * 864 + tid;
        int nsi = j / 54, kq = j % 54;
        __half2 h0 = __floats2half2_rn(sbuf[(kq * 4 + 0) * 33 + nsi],
                                       sbuf[(kq * 4 + 1) * 33 + nsi]);
        __half2 h1 = __floats2half2_rn(sbuf[(kq * 4 + 2) * 33 + nsi],
                                       sbuf[(kq * 4 + 3) * 33 + nsi]);
        *(uint2*)&cols[(size_t)(nsb + nsi) * K + g * 216 + kq * 4] =
            make_uint2(h2_as_u32(h0), h2_as_u32(h1));
    }
}

// ---------------------------------------------------------------------------
// Deformable im2col (fp16 input) -> cols[ns][K] (half), smem staged.
// ---------------------------------------------------------------------------
__global__ __launch_bounds__(864) void deform_T(
    const __half* __restrict__ in, const float* __restrict__ off,
    __half* __restrict__ cols, int C, int G, int Din, int Hin, int Win,
    int stride, int ncdhw) {
    __shared__ float sbuf[216 * 33];
    int K = C * 27;
    int tid = threadIdx.x;
    int nsl = tid & 31, tap = tid >> 5;
    int nsb = blockIdx.x * 32, g = blockIdx.y;
    int ns = nsb + nsl;
    int n = ns / S_OUT, s = ns % S_OUT;
    int od = s / (OH * OW), oh = (s / OW) % OH, ow = s % OW;
    int kd = tap / 9, kh = (tap / 3) % 3, kw = tap % 3;

    size_t ob = ((size_t)(g * 3) * 27 + tap) * NS + ns;
    float pd = off[ob]                   + (float)(od * stride - 1 + kd);
    float ph = off[ob + (size_t)27 * NS] + (float)(oh * stride - 1 + kh);
    float pw = off[ob + (size_t)54 * NS] + (float)(ow * stride - 1 + kw);
    float d0f = floorf(pd), h0f = floorf(ph), w0f = floorf(pw);
    int d0 = (int)d0f, h0 = (int)h0f, w0 = (int)w0f;
    float fd = pd - d0f, fh = ph - h0f, fw = pw - w0f;

    float wt8[8]; int idx8[8];
    int Sin = Din * Hin * Win;
#pragma unroll
    for (int cr = 0; cr < 8; cr++) {
        int cd = cr >> 2, ch = (cr >> 1) & 1, cw = cr & 1;
        int di = d0 + cd, hi = h0 + ch, wi = w0 + cw;
        bool valid = (di >= 0) && (di < Din) && (hi >= 0) && (hi < Hin) &&
                     (wi >= 0) && (wi < Win);
        float wt = (cd ? fd : 1.f - fd) * (ch ? fh : 1.f - fh) * (cw ? fw : 1.f - fw);
        wt8[cr] = valid ? wt : 0.f;
        int dic = di < 0 ? 0 : (di > Din - 1 ? Din - 1 : di);
        int hic = hi < 0 ? 0 : (hi > Hin - 1 ? Hin - 1 : hi);
        int wic = wi < 0 ? 0 : (wi > Win - 1 ? Win - 1 : wi);
        idx8[cr] = (dic * Hin + hic) * Win + wic;
    }
#pragma unroll
    for (int cc = 0; cc < 8; cc++) {
        int c = g * 8 + cc;
        size_t base = ncdhw ? ((size_t)(n * C + c)) * Sin : ((size_t)c * NBATCH + n) * Sin;
        const __half* bp = in + base;
        float acc = 0.f;
#pragma unroll
        for (int cr = 0; cr < 8; cr++) acc += wt8[cr] * __half2float(bp[idx8[cr]]);
        sbuf[(cc * 27 + tap) * 33 + nsl] = acc;
    }
    __syncthreads();
#pragma unroll
    for (int it = 0; it < 2; it++) {
        int j = it * 864 + tid;
        int nsi = j / 54, kq = j % 54;
        __half2 h0 = __floats2half2_rn(sbuf[(kq * 4 + 0) * 33 + nsi],
                                       sbuf[(kq * 4 + 1) * 33 + nsi]);
        __half2 h1 = __floats2half2_rn(sbuf[(kq * 4 + 2) * 33 + nsi],
                                       sbuf[(kq * 4 + 3) * 33 + nsi]);
        *(uint2*)&cols[(size_t)(nsb + nsi) * K + g * 216 + kq * 4] =
            make_uint2(h2_as_u32(h0), h2_as_u32(h1));
    }
}

// ---------------------------------------------------------------------------
// FP16 mma.sync GEMM, 512 threads / 16 warps (2x8), ldmatrix fragment loads.
// C[M][NS] = A[M][K]*B^T (+bias). BM=128, BN {128,256}, BK=32,
// 4-stage cp.async (3 in flight), one sync per k-tile, warp tile 64x(BN/8).
// ---------------------------------------------------------------------------
#define HBK 32
#define HPH 40
#define GST 4
#define GTH 512

__device__ __forceinline__ void cpasync16h(__half* dst, const __half* src, bool pred) {
    uint32_t d = (uint32_t)__cvta_generic_to_shared(dst);
    int sz = pred ? 16 : 0;
    asm volatile("cp.async.cg.shared.global [%0], [%1], 16, %2;\n"
                 :: "r"(d), "l"(src), "r"(sz));
}
__device__ __forceinline__ void mma_f16(float* c, uint32_t a0, uint32_t a1,
                                        uint32_t a2, uint32_t a3,
                                        uint32_t b0, uint32_t b1) {
    asm volatile(
        "mma.sync.aligned.m16n8k16.row.col.f32.f16.f16.f32 "
        "{%0,%1,%2,%3}, {%4,%5,%6,%7}, {%8,%9}, {%0,%1,%2,%3};\n"
        : "+f"(c[0]), "+f"(c[1]), "+f"(c[2]), "+f"(c[3])
        : "r"(a0), "r"(a1), "r"(a2), "r"(a3), "r"(b0), "r"(b1));
}
__device__ __forceinline__ void ldsm_x4(uint32_t* r, uint32_t addr) {
    asm volatile("ldmatrix.sync.aligned.m8n8.x4.shared.b16 {%0,%1,%2,%3}, [%4];"
                 : "=r"(r[0]), "=r"(r[1]), "=r"(r[2]), "=r"(r[3]) : "r"(addr));
}

template <int BN>
__global__ __launch_bounds__(GTH) void gemm_h(
    const __half* __restrict__ A, const __half* __restrict__ B,
    const float* __restrict__ bias, float* __restrict__ C, int M, int K) {
    constexpr int BM = 128;
    constexpr int WN = BN / 8;      // 32 or 16
    constexpr int NT = WN / 8;      // 4 or 2
    constexpr int NB2 = NT / 2;     // B ldsm.x4 per ks: 2 or 1
    constexpr int AH = BM * HPH;
    constexpr int BH = BN * HPH;
    constexpr int ASL = BM * HBK / 8 / GTH;   // 1
    constexpr int BSL = BN * HBK / 8 / GTH;   // 2 (BN=256) or 1

    extern __shared__ __half smh[];
    __half* Asm = smh;
    __half* Bsm = smh + GST * AH;

    int tid = threadIdx.x;
    int warp = tid >> 5, lane = tid & 31;
    int wm = warp >> 3, wn = warp & 7;     // 2 x 8 warps
    int rg = lane >> 2, cg = lane & 3;
    int row0 = blockIdx.x * BM;
    int col0 = blockIdx.y * BN;
    int T = K / HBK;

    // cp.async slot geometry
    int am[ASL], akq[ASL]; bool aok[ASL];
    const __half* asrc[ASL];
#pragma unroll
    for (int u = 0; u < ASL; u++) {
        int slot = u * GTH + tid;
        am[u] = slot >> 2; akq[u] = slot & 3;
        int gm = row0 + am[u];
        aok[u] = gm < M;
        asrc[u] = A + (size_t)(aok[u] ? gm : 0) * K + akq[u] * 8;
    }
    int bn_[BSL], bkq[BSL];
    const __half* bsrc[BSL];
#pragma unroll
    for (int u = 0; u < BSL; u++) {
        int slot = u * GTH + tid;
        bn_[u] = slot >> 2; bkq[u] = slot & 3;
        bsrc[u] = B + (size_t)(col0 + bn_[u]) * K + bkq[u] * 8;
    }

    // ldmatrix per-thread byte offsets within a stage (ks=0; ks=1 adds 32B)
    uint32_t aBase = (uint32_t)__cvta_generic_to_shared(Asm);
    uint32_t bBase = (uint32_t)__cvta_generic_to_shared(Bsm);
    uint32_t aOff[4];
#pragma unroll
    for (int i = 0; i < 4; i++) {
        int row = wm * 64 + i * 16 + (lane & 15);
        int col = (lane >> 4) << 3;
        aOff[i] = (uint32_t)((row * HPH + col) * 2);
    }
    uint32_t bOff[NB2];
#pragma unroll
    for (int p = 0; p < NB2; p++) {
        int row = wn * WN + p * 16 + (lane & 7) + ((lane & 16) ? 8 : 0);
        int col = (lane & 8) ? 8 : 0;
        bOff[p] = (uint32_t)((row * HPH + col) * 2);
    }

    float acc[4][NT][4];
#pragma unroll
    for (int i = 0; i < 4; i++)
#pragma unroll
        for (int j = 0; j < NT; j++)
#pragma unroll
            for (int r = 0; r < 4; r++) acc[i][j][r] = 0.f;

    // prologue: tiles 0..GST-2
#pragma unroll
    for (int t = 0; t < GST - 1; t++) {
#pragma unroll
        for (int u = 0; u < ASL; u++)
            cpasync16h(&Asm[t * AH + am[u] * HPH + akq[u] * 8], asrc[u] + t * HBK, aok[u]);
#pragma unroll
        for (int u = 0; u < BSL; u++)
            cpasync16h(&Bsm[t * BH + bn_[u] * HPH + bkq[u] * 8], bsrc[u] + t * HBK, true);
        asm volatile("cp.async.commit_group;\n");
    }

    for (int t = 0; t < T; t++) {
        asm volatile("cp.async.wait_group 2;\n");
        __syncthreads();
        int st = t % GST;
        uint32_t aS = aBase + (uint32_t)(st * AH * 2);
        uint32_t bS = bBase + (uint32_t)(st * BH * 2);

#pragma unroll
        for (int ks = 0; ks < 2; ks++) {
            uint32_t kadd = ks * 32;
            uint32_t af[4][4], bf[NB2][4];
#pragma unroll
            for (int i = 0; i < 4; i++) ldsm_x4(af[i], aS + aOff[i] + kadd);
#pragma unroll
            for (int p = 0; p < NB2; p++) ldsm_x4(bf[p], bS + bOff[p] + kadd);
#pragma unroll
            for (int i = 0; i < 4; i++)
#pragma unroll
                for (int p = 0; p < NB2; p++) {
                    mma_f16(acc[i][2 * p],     af[i][0], af[i][1], af[i][2], af[i][3],
                            bf[p][0], bf[p][1]);
                    mma_f16(acc[i][2 * p + 1], af[i][0], af[i][1], af[i][2], af[i][3],
                            bf[p][2], bf[p][3]);
                }
        }

        int tn = t + GST - 1;
        if (tn < T) {
            int sn = tn % GST;
            int k0 = tn * HBK;
#pragma unroll
            for (int u = 0; u < ASL; u++)
                cpasync16h(&Asm[sn * AH + am[u] * HPH + akq[u] * 8], asrc[u] + k0, aok[u]);
#pragma unroll
            for (int u = 0; u < BSL; u++)
                cpasync16h(&Bsm[sn * BH + bn_[u] * HPH + bkq[u] * 8], bsrc[u] + k0, true);
        }
        asm volatile("cp.async.commit_group;\n");
    }

    // epilogue
#pragma unroll
    for (int i = 0; i < 4; i++) {
        int gm0 = row0 + wm * 64 + i * 16 + rg;
        int gm1 = gm0 + 8;
        float bv0 = (bias && gm0 < M) ? bias[gm0] : 0.f;
        float bv1 = (bias && gm1 < M) ? bias[gm1] : 0.f;
#pragma unroll
        for (int j = 0; j < NT; j++) {
            int gc = col0 + wn * WN + j * 8 + 2 * cg;
            if (gm0 < M)
                *(float2*)&C[(size_t)gm0 * NS + gc] =
                    make_float2(acc[i][j][0] + bv0, acc[i][j][1] + bv0);
            if (gm1 < M)
                *(float2*)&C[(size_t)gm1 * NS + gc] =
                    make_float2(acc[i][j][2] + bv1, acc[i][j][3] + bv1);
        }
    }
}

#define SMEMH256 (GST * (128 * HPH + 256 * HPH) * 2)   // 122880
#define SMEMH128 (GST * (128 * HPH + 128 * HPH) * 2)   // 81920

// ---------------- BN stats / final ----------------
__global__ void bn_stats(const float* __restrict__ x, float* __restrict__ mean,
                         float* __restrict__ istd) {
    int c = blockIdx.x;
    const float* row = x + (size_t)c * NS;
    float s = 0.f, s2 = 0.f;
    for (int i = threadIdx.x; i < NS / 4; i += blockDim.x) {
        float4 v = ((const float4*)row)[i];
        s += v.x + v.y + v.z + v.w;
        s2 += v.x * v.x + v.y * v.y + v.z * v.z + v.w * v.w;
    }
    __shared__ float sh[256], sh2[256];
    sh[threadIdx.x] = s; sh2[threadIdx.x] = s2;
    __syncthreads();
    for (int st = 128; st > 0; st >>= 1) {
        if (threadIdx.x < st) {
            sh[threadIdx.x] += sh[threadIdx.x + st];
            sh2[threadIdx.x] += sh2[threadIdx.x + st];
        }
        __syncthreads();
    }
    if (threadIdx.x == 0) {
        float m = sh[0] / (float)NS;
        float var = sh2[0] / (float)NS - m * m;
        mean[c] = m;
        istd[c] = rsqrtf(var + 1e-5f);
    }
}

__global__ void final_kernel(const float* __restrict__ raw, const float* __restrict__ gam,
                             const float* __restrict__ bet, const float* __restrict__ mean,
                             const float* __restrict__ istd, const float* __restrict__ res,
                             float* __restrict__ out) {
    int i = blockIdx.x * blockDim.x + threadIdx.x;
    if (i >= 128 * NS) return;
    int n = i / (128 * S_OUT);
    int co = (i / S_OUT) % 128;
    int s = i % S_OUT;
    float v = (raw[(size_t)co * NS + n * S_OUT + s] - mean[co]) * istd[co] * gam[co] + bet[co];
    v += res[(size_t)(co & 63) * NS + n * S_OUT + s];
    out[i] = fmaxf(v, 0.f);
}

// ---------------- host ----------------
extern "C" void kernel_launch(void* const* d_in, const int* in_sizes, int n_in,
                              void* d_out, int out_size) {
    (void)in_sizes; (void)n_in; (void)out_size;
    const float* x       = (const float*)d_in[0];
    const float* off1_w  = (const float*)d_in[1];
    const float* off1_b  = (const float*)d_in[2];
    const float* conv1_w = (const float*)d_in[3];
    const float* bn1_g   = (const float*)d_in[4];
    const float* bn1_b   = (const float*)d_in[5];
    const float* off2_w  = (const float*)d_in[6];
    const float* off2_b  = (const float*)d_in[7];
    const float* conv2_w = (const float*)d_in[8];
    const float* bn2_g   = (const float*)d_in[9];
    const float* bn2_b   = (const float*)d_in[10];
    float* out = (float*)d_out;

    __half *cols, *wh, *xh, *act;
    float *off1, *off2, *out1, *out2, *res, *mean, *istd;
    cudaGetSymbolAddress((void**)&cols, g_cols);
    cudaGetSymbolAddress((void**)&wh,   g_wh);
    cudaGetSymbolAddress((void**)&xh,   g_xh);
    cudaGetSymbolAddress((void**)&act,  g_act);
    cudaGetSymbolAddress((void**)&off1, g_off1);
    cudaGetSymbolAddress((void**)&off2, g_off2);
    cudaGetSymbolAddress((void**)&out1, g_out1);
    cudaGetSymbolAddress((void**)&out2, g_out2);
    cudaGetSymbolAddress((void**)&res,  g_res);
    cudaGetSymbolAddress((void**)&mean, g_mean);
    cudaGetSymbolAddress((void**)&istd, g_istd);

    static int attr_done = 0;
    if (!attr_done) {
        cudaFuncSetAttribute(gemm_h<256>, cudaFuncAttributeMaxDynamicSharedMemorySize, SMEMH256);
        cudaFuncSetAttribute(gemm_h<128>, cudaFuncAttributeMaxDynamicSharedMemorySize, SMEMH128);
        attr_done = 1;
    }

    const int T = 256;
    const int n4all = (N_OFF1W + N_CV1W + N_OFF2W + N_CV2W) / 4;

    // launch 1: all weights -> half
    f2h_all<<<(n4all + T - 1) / T, T>>>(off1_w, conv1_w, off2_w, conv2_w, wh);
    // launch 2: x -> half
    f2h4_kernel<<<(6422528 / 4 + T - 1) / T, T>>>(x, xh, 6422528 / 4);
    // launch 3: im2col for off1
    im2col_blk<64, 2, 1><<<dim3(NS / 32, 8), 864>>>(xh, cols, 16, 56, 56);
    // launch 4 (profiled by ncu): off1 GEMM, M=648, K=1728
    gemm_h<256><<<dim3(6, NS / 256), GTH, SMEMH256>>>(wh + WH_OFF1, cols, off1_b, off1, 648, 1728);
    // launch 5: residual maxpool (independent)
    maxpool_kernel<<<(64 * NS + T - 1) / T, T>>>(x, res);

    // out1 = deform_conv3d(x, off1, stride=2): M=128, K=1728
    deform_T<<<dim3(NS / 32, 8), 864>>>(xh, off1, cols, 64, 8, 16, 56, 56, 2, 1);
    gemm_h<128><<<dim3(1, NS / 128), GTH, SMEMH128>>>(wh + WH_CV1, cols, nullptr, out1, 128, 1728);

    bn_stats<<<128, 256>>>(out1, mean, istd);
    bn_act_h<<<(128 * NS / 4 + T - 1) / T, T>>>(out1, act, bn1_g, bn1_b, mean, istd);

    // off2 = conv3d(act, stride=1): M=1296, K=3456
    im2col_blk<128, 1, 0><<<dim3(NS / 32, 16), 864>>>(act, cols, 8, 28, 28);
    gemm_h<256><<<dim3(11, NS / 256), GTH, SMEMH256>>>(wh + WH_OFF2, cols, off2_b, off2, 1296, 3456);

    // out2 = deform_conv3d(act, off2, stride=1): M=128, K=3456
    deform_T<<<dim3(NS / 32, 16), 864>>>(act, off2, cols, 128, 16, 8, 28, 28, 1, 0);
    gemm_h<128><<<dim3(1, NS / 128), GTH, SMEMH128>>>(wh + WH_CV2, cols, nullptr, out2, 128, 3456);

    bn_stats<<<128, 256>>>(out2, mean, istd);
    final_kernel<<<(128 * NS + T - 1) / T, T>>>(out2, bn2_g, bn2_b, mean, istd, res, out);
}